// round 1
// baseline (speedup 1.0000x reference)
#include <cuda_runtime.h>
#include <math.h>

#define NN 50000
#define EE 1600000
#define ETOT (EE + NN)

// ---------------- scratch (static device globals; no allocation) ----------------
__device__ float g_h[NN * 64];      // per-layer GEMM output h = x @ W
__device__ float g_x2[NN * 64];     // activations between layers
__device__ float g_als[NN * 4];     // per-node src attention logits
__device__ float g_ald[NN * 4];     // per-node dst attention logits
__device__ float g_denom[NN * 4];   // softmax denominators
__device__ float g_acc[NN * 64];    // aggregated messages
__device__ float g_ex[ETOT * 4];    // per-edge exp(e) values

// ---------------- zero scratch ----------------
__global__ void zero_kernel(int outw, int H) {
    int i = blockIdx.x * blockDim.x + threadIdx.x;
    int stride = gridDim.x * blockDim.x;
    for (int idx = i; idx < NN * outw; idx += stride) g_acc[idx] = 0.f;
    for (int idx = i; idx < NN * H; idx += stride) g_denom[idx] = 0.f;
}

// ---------------- GEMM: Hout[N,OUT] = X[N,IN] @ W[IN,OUT] ----------------
template <int IN, int OUT>
__global__ void gemm_kernel(const float* __restrict__ X, const float* __restrict__ W,
                            float* __restrict__ Hout) {
    constexpr int RY = 256 / OUT;   // thread row-groups
    constexpr int RPT = 4;          // rows per thread
    constexpr int RB = RY * RPT;    // rows per block
    __shared__ float sW[IN * OUT];
    __shared__ float sX[RB * IN];
    int t = threadIdx.x;
    int tx = t % OUT, ty = t / OUT;
    int row0 = blockIdx.x * RB;

    for (int i = t; i < IN * OUT; i += 256) sW[i] = W[i];
    for (int i = t; i < RB * IN; i += 256) {
        int r = row0 + i / IN;
        sX[i] = (r < NN) ? X[r * IN + (i % IN)] : 0.f;
    }
    __syncthreads();

    float acc[RPT];
#pragma unroll
    for (int rr = 0; rr < RPT; rr++) acc[rr] = 0.f;
    const float* xs = &sX[ty * RPT * IN];
    for (int k = 0; k < IN; k++) {
        float wv = sW[k * OUT + tx];
#pragma unroll
        for (int rr = 0; rr < RPT; rr++) acc[rr] += xs[rr * IN + k] * wv;
    }
#pragma unroll
    for (int rr = 0; rr < RPT; rr++) {
        int r = row0 + ty * RPT + rr;
        if (r < NN) Hout[r * OUT + tx] = acc[rr];
    }
}

// ---------------- per-node attention logits ----------------
template <int H, int C>
__global__ void al_kernel(const float* __restrict__ Hm, const float* __restrict__ a_s,
                          const float* __restrict__ a_d) {
    int n = blockIdx.x * blockDim.x + threadIdx.x;
    if (n >= NN) return;
#pragma unroll
    for (int h = 0; h < H; h++) {
        float s = 0.f, d = 0.f;
#pragma unroll
        for (int c = 0; c < C; c++) {
            float hv = Hm[n * H * C + h * C + c];
            s += hv * __ldg(&a_s[h * C + c]);
            d += hv * __ldg(&a_d[h * C + c]);
        }
        g_als[n * H + h] = s;
        g_ald[n * H + h] = d;
    }
}

// ---------------- edge pass A: e -> exp -> denom ----------------
__device__ __forceinline__ float lrelu_exp(float v) {
    v = (v > 0.f) ? v : 0.2f * v;
    return __expf(v);
}

template <int H>
__global__ void edge_a(const int* __restrict__ ei) {
    int e = blockIdx.x * blockDim.x + threadIdx.x;
    if (e >= ETOT) return;
    int s, d;
    if (e < EE) { s = ei[e]; d = ei[EE + e]; } else { s = e - EE; d = s; }
    if (H == 4) {
        float4 as4 = *(const float4*)&g_als[s * 4];
        float4 ad4 = *(const float4*)&g_ald[d * 4];
        float4 ex;
        ex.x = lrelu_exp(as4.x + ad4.x);
        ex.y = lrelu_exp(as4.y + ad4.y);
        ex.z = lrelu_exp(as4.z + ad4.z);
        ex.w = lrelu_exp(as4.w + ad4.w);
        *(float4*)&g_ex[e * 4] = ex;
        atomicAdd((float4*)&g_denom[d * 4], ex);
    } else {
        float ex = lrelu_exp(g_als[s] + g_ald[d]);
        g_ex[e] = ex;
        atomicAdd(&g_denom[d], ex);
    }
}

// ---------------- edge pass C: acc[dst] += alpha * h[src] ----------------
template <int OUTW>
__global__ void edge_c(const int* __restrict__ ei) {
    constexpr int LPE = OUTW / 4;   // lanes (float4 chunks) per edge
    constexpr int H = OUTW / 16;
    int tid = blockIdx.x * blockDim.x + threadIdx.x;
    int e = tid / LPE;
    int j = tid % LPE;
    if (e >= ETOT) return;
    int s, d;
    if (e < EE) { s = ei[e]; d = ei[EE + e]; } else { s = e - EE; d = s; }
    int head = j >> 2;              // OUTW=16 -> always 0
    float ex = g_ex[e * H + head];
    float den = g_denom[d * H + head];
    float alpha = ex / (den + 1e-16f);
    float4 hv = *(const float4*)&g_h[s * OUTW + j * 4];
    float4 v;
    v.x = hv.x * alpha; v.y = hv.y * alpha; v.z = hv.z * alpha; v.w = hv.w * alpha;
    atomicAdd((float4*)&g_acc[d * OUTW + j * 4], v);
}

// ---------------- epilogue layers 1/2: bias + BN + ReLU ----------------
__global__ void ep12(const float* __restrict__ b, const float* __restrict__ gg,
                     const float* __restrict__ bb, const float* __restrict__ mm,
                     const float* __restrict__ vv, float* __restrict__ xnext) {
    int tid = blockIdx.x * blockDim.x + threadIdx.x;
    if (tid >= NN * 16) return;
    int n = tid >> 4;
    int jj = tid & 15;
    int c0 = jj * 4;
    float4 a = *(const float4*)&g_acc[n * 64 + c0];
    float4 o;
    float* ap = &a.x;
    float* op = &o.x;
#pragma unroll
    for (int c = 0; c < 4; c++) {
        int col = c0 + c;
        float y = (ap[c] + __ldg(&b[col]) - __ldg(&mm[col])) *
                      rsqrtf(__ldg(&vv[col]) + 1e-5f) * __ldg(&gg[col]) +
                  __ldg(&bb[col]);
        op[c] = fmaxf(y, 0.f);
    }
    *(float4*)&xnext[n * 64 + c0] = o;
}

// ---------------- epilogue layer 3: bias + BN + ReLU + fc1 + ReLU + fc2 ----------------
__global__ void ep3(const float* __restrict__ b3, const float* __restrict__ gg,
                    const float* __restrict__ bb, const float* __restrict__ mm,
                    const float* __restrict__ vv, const float* __restrict__ fw1,
                    const float* __restrict__ fb1, const float* __restrict__ fw2,
                    const float* __restrict__ fb2, float* __restrict__ out) {
    int n = blockIdx.x * blockDim.x + threadIdx.x;
    if (n >= NN) return;
    float t[16];
#pragma unroll
    for (int c = 0; c < 16; c++) {
        float y = (g_acc[n * 16 + c] + __ldg(&b3[c]) - __ldg(&mm[c])) *
                      rsqrtf(__ldg(&vv[c]) + 1e-5f) * __ldg(&gg[c]) +
                  __ldg(&bb[c]);
        t[c] = fmaxf(y, 0.f);
    }
    float o = __ldg(&fb2[0]);
#pragma unroll
    for (int oo = 0; oo < 8; oo++) {
        float z = __ldg(&fb1[oo]);
#pragma unroll
        for (int c = 0; c < 16; c++) z += t[c] * __ldg(&fw1[c * 8 + oo]);
        z = fmaxf(z, 0.f);
        o += z * __ldg(&fw2[oo]);
    }
    out[n] = o;
}

// ---------------- launch ----------------
extern "C" void kernel_launch(void* const* d_in, const int* in_sizes, int n_in,
                              void* d_out, int out_size) {
    const float* x = (const float*)d_in[0];
    const int* ei = (const int*)d_in[1];
    const float* W1 = (const float*)d_in[2];
    const float* as1 = (const float*)d_in[3];
    const float* ad1 = (const float*)d_in[4];
    const float* b1 = (const float*)d_in[5];
    const float* g1 = (const float*)d_in[6];
    const float* bb1 = (const float*)d_in[7];
    const float* m1 = (const float*)d_in[8];
    const float* v1 = (const float*)d_in[9];
    const float* W2 = (const float*)d_in[10];
    const float* as2 = (const float*)d_in[11];
    const float* ad2 = (const float*)d_in[12];
    const float* b2 = (const float*)d_in[13];
    const float* g2 = (const float*)d_in[14];
    const float* bb2 = (const float*)d_in[15];
    const float* m2 = (const float*)d_in[16];
    const float* v2 = (const float*)d_in[17];
    const float* W3 = (const float*)d_in[18];
    const float* as3 = (const float*)d_in[19];
    const float* ad3 = (const float*)d_in[20];
    const float* b3 = (const float*)d_in[21];
    const float* g3 = (const float*)d_in[22];
    const float* bb3 = (const float*)d_in[23];
    const float* m3 = (const float*)d_in[24];
    const float* v3 = (const float*)d_in[25];
    const float* fw1 = (const float*)d_in[26];
    const float* fb1 = (const float*)d_in[27];
    const float* fw2 = (const float*)d_in[28];
    const float* fb2 = (const float*)d_in[29];
    float* out = (float*)d_out;

    float* ph = nullptr;
    float* px2 = nullptr;
    cudaGetSymbolAddress((void**)&ph, g_h);
    cudaGetSymbolAddress((void**)&px2, g_x2);

    const int TB = 256;
    int nblk = (NN + TB - 1) / TB;
    int eblk = (ETOT + TB - 1) / TB;
    int ec64 = (ETOT * 16 + TB - 1) / TB;
    int ec16 = (ETOT * 4 + TB - 1) / TB;
    int epblk = (NN * 16 + TB - 1) / TB;

    // ---- Layer 1 ----
    gemm_kernel<128, 64><<<(NN + 15) / 16, TB>>>(x, W1, ph);
    al_kernel<4, 16><<<nblk, TB>>>(ph, as1, ad1);
    zero_kernel<<<2048, TB>>>(64, 4);
    edge_a<4><<<eblk, TB>>>(ei);
    edge_c<64><<<ec64, TB>>>(ei);
    ep12<<<epblk, TB>>>(b1, g1, bb1, m1, v1, px2);

    // ---- Layer 2 ----
    gemm_kernel<64, 64><<<(NN + 15) / 16, TB>>>(px2, W2, ph);
    al_kernel<4, 16><<<nblk, TB>>>(ph, as2, ad2);
    zero_kernel<<<2048, TB>>>(64, 4);
    edge_a<4><<<eblk, TB>>>(ei);
    edge_c<64><<<ec64, TB>>>(ei);
    ep12<<<epblk, TB>>>(b2, g2, bb2, m2, v2, px2);

    // ---- Layer 3 ----
    gemm_kernel<64, 16><<<(NN + 63) / 64, TB>>>(px2, W3, ph);
    al_kernel<1, 16><<<nblk, TB>>>(ph, as3, ad3);
    zero_kernel<<<2048, TB>>>(16, 1);
    edge_a<1><<<eblk, TB>>>(ei);
    edge_c<16><<<ec16, TB>>>(ei);
    ep3<<<nblk, TB>>>(b3, g3, bb3, m3, v3, fw1, fb1, fw2, fb2, out);
}

// round 3
// speedup vs baseline: 1.0218x; 1.0218x over previous
#include <cuda_runtime.h>
#include <math.h>

#define NN 50000
#define EE 1600000
#define ETOT (EE + NN)

// ---------------- scratch (static device globals; no allocation) ----------------
__device__ float g_h[NN * 64];      // per-layer GEMM output h = x @ W
__device__ float g_x2[NN * 64];     // activations between layers
__device__ float g_als[NN * 4];     // per-node src attention logits
__device__ float g_ald[NN * 4];     // per-node dst attention logits
__device__ float g_acc[NN * 16];    // layer-3 aggregated output (normalized)
__device__ int   g_deg[NN];         // in-degree histogram
__device__ int   g_off[NN + 1];     // CSR offsets (by dst)
__device__ int   g_cur[NN];         // scatter cursors
__device__ int   g_csr[ETOT];       // src node per incoming edge, grouped by dst

// ================= CSR build (once per launch; reused by all 3 layers) =========
__global__ void hist_kernel(const int* __restrict__ ei) {
    int e = blockIdx.x * blockDim.x + threadIdx.x;
    if (e >= ETOT) return;
    int d = (e < EE) ? ei[EE + e] : (e - EE);
    atomicAdd(&g_deg[d], 1);
}

__global__ void scan_kernel() {
    __shared__ int partial[1024];
    int t = threadIdx.x;
    const int C = (NN + 1023) / 1024;      // 49
    int b0 = t * C;
    int b1 = min(b0 + C, NN);
    int sum = 0;
    for (int i = b0; i < b1; i++) sum += g_deg[i];
    partial[t] = sum;
    __syncthreads();
    for (int off = 1; off < 1024; off <<= 1) {
        int v = (t >= off) ? partial[t - off] : 0;
        __syncthreads();
        partial[t] += v;
        __syncthreads();
    }
    int run = (t == 0) ? 0 : partial[t - 1];
    for (int i = b0; i < b1; i++) {
        g_off[i] = run;
        g_cur[i] = run;
        run += g_deg[i];
    }
    if (t == 1023) g_off[NN] = run;        // == ETOT
}

__global__ void scatter_kernel(const int* __restrict__ ei) {
    int e = blockIdx.x * blockDim.x + threadIdx.x;
    if (e >= ETOT) return;
    int s, d;
    if (e < EE) { s = ei[e]; d = ei[EE + e]; } else { s = e - EE; d = s; }
    int pos = atomicAdd(&g_cur[d], 1);
    g_csr[pos] = s;
}

// ---------------- GEMM: Hout[N,OUT] = X[N,IN] @ W[IN,OUT] ----------------
template <int IN, int OUT>
__global__ void gemm_kernel(const float* __restrict__ X, const float* __restrict__ W,
                            float* __restrict__ Hout) {
    constexpr int RY = 256 / OUT;
    constexpr int RPT = 4;
    constexpr int RB = RY * RPT;
    __shared__ float sW[IN * OUT];
    __shared__ float sX[RB * IN];
    int t = threadIdx.x;
    int tx = t % OUT, ty = t / OUT;
    int row0 = blockIdx.x * RB;

    for (int i = t; i < IN * OUT; i += 256) sW[i] = W[i];
    for (int i = t; i < RB * IN; i += 256) {
        int r = row0 + i / IN;
        sX[i] = (r < NN) ? X[r * IN + (i % IN)] : 0.f;
    }
    __syncthreads();

    float acc[RPT];
#pragma unroll
    for (int rr = 0; rr < RPT; rr++) acc[rr] = 0.f;
    const float* xs = &sX[ty * RPT * IN];
    for (int k = 0; k < IN; k++) {
        float wv = sW[k * OUT + tx];
#pragma unroll
        for (int rr = 0; rr < RPT; rr++) acc[rr] += xs[rr * IN + k] * wv;
    }
#pragma unroll
    for (int rr = 0; rr < RPT; rr++) {
        int r = row0 + ty * RPT + rr;
        if (r < NN) Hout[r * OUT + tx] = acc[rr];
    }
}

// ---------------- per-node attention logits ----------------
template <int H, int C>
__global__ void al_kernel(const float* __restrict__ Hm, const float* __restrict__ a_s,
                          const float* __restrict__ a_d) {
    int n = blockIdx.x * blockDim.x + threadIdx.x;
    if (n >= NN) return;
#pragma unroll
    for (int h = 0; h < H; h++) {
        float s = 0.f, d = 0.f;
#pragma unroll
        for (int c = 0; c < C; c++) {
            float hv = Hm[n * H * C + h * C + c];
            s += hv * __ldg(&a_s[h * C + c]);
            d += hv * __ldg(&a_d[h * C + c]);
        }
        g_als[n * H + h] = s;
        g_ald[n * H + h] = d;
    }
}

__device__ __forceinline__ float lrelu_exp(float v) {
    v = (v > 0.f) ? v : 0.2f * v;
    return __expf(v);
}

// ============ fused gather-aggregation, 64-wide (layers 1 & 2) ============
// warp per dst node; lane owns cols (lane, lane+32) -> heads (lane>>4, 2+(lane>>4)).
// acc = sum_e ex_e * h[src_e]; den = sum_e ex_e; out = relu(BN(acc/den + b)).
__global__ void __launch_bounds__(256)
agg64(const float* __restrict__ Hm, const float* __restrict__ b,
      const float* __restrict__ gg, const float* __restrict__ bb,
      const float* __restrict__ mm, const float* __restrict__ vv,
      float* __restrict__ xnext) {
    int warp = (blockIdx.x * blockDim.x + threadIdx.x) >> 5;
    int lane = threadIdx.x & 31;
    if (warp >= NN) return;
    int n = warp;
    int c0 = lane, c1 = lane + 32;
    int h0 = lane >> 4, h1 = 2 + (lane >> 4);
    float ad0 = g_ald[n * 4 + h0];
    float ad1 = g_ald[n * 4 + h1];
    float acc0 = 0.f, acc1 = 0.f, den0 = 0.f, den1 = 0.f;
    int beg = g_off[n], end = g_off[n + 1];
    for (int base = beg; base < end; base += 32) {
        int idx = base + lane;
        int sl = (idx < end) ? g_csr[idx] : 0;
        int nk = min(32, end - base);
        for (int j = 0; j < nk; j++) {
            int s = __shfl_sync(0xffffffffu, sl, j);
            float e0 = __ldg(&g_als[s * 4 + h0]) + ad0;
            float e1 = __ldg(&g_als[s * 4 + h1]) + ad1;
            float ex0 = lrelu_exp(e0);
            float ex1 = lrelu_exp(e1);
            den0 += ex0;
            den1 += ex1;
            acc0 += ex0 * __ldg(&Hm[s * 64 + c0]);
            acc1 += ex1 * __ldg(&Hm[s * 64 + c1]);
        }
    }
    float r0 = acc0 / (den0 + 1e-16f);
    float r1 = acc1 / (den1 + 1e-16f);
    float y0 = (r0 + __ldg(&b[c0]) - __ldg(&mm[c0])) * rsqrtf(__ldg(&vv[c0]) + 1e-5f) *
                   __ldg(&gg[c0]) + __ldg(&bb[c0]);
    float y1 = (r1 + __ldg(&b[c1]) - __ldg(&mm[c1])) * rsqrtf(__ldg(&vv[c1]) + 1e-5f) *
                   __ldg(&gg[c1]) + __ldg(&bb[c1]);
    xnext[n * 64 + c0] = fmaxf(y0, 0.f);
    xnext[n * 64 + c1] = fmaxf(y1, 0.f);
}

// ============ fused gather-aggregation, 16-wide (layer 3) ============
// warp per dst node. Two edges processed per (uniform) j-iteration: the low
// 16 lanes take edge j, the high 16 lanes take edge j+1 (predicated off if
// j+1 >= nk). All __shfl_sync calls are executed from converged code.
__global__ void __launch_bounds__(256)
agg16(const float* __restrict__ Hm) {
    int warp = (blockIdx.x * blockDim.x + threadIdx.x) >> 5;
    int lane = threadIdx.x & 31;
    if (warp >= NN) return;
    int n = warp;
    int c = lane & 15;
    int half = lane >> 4;
    float ad = g_ald[n];
    float acc = 0.f, den = 0.f;
    int beg = g_off[n], end = g_off[n + 1];
    for (int base = beg; base < end; base += 32) {
        int idx = base + lane;
        int sl = (idx < end) ? g_csr[idx] : 0;
        int nk = min(32, end - base);
        for (int j = 0; j < nk; j += 2) {
            int s0 = __shfl_sync(0xffffffffu, sl, j);
            int s1 = __shfl_sync(0xffffffffu, sl, (j + 1 < 32) ? (j + 1) : j);
            int s = half ? s1 : s0;
            bool valid = (half == 0) || (j + 1 < nk);
            if (valid) {
                float e = __ldg(&g_als[s]) + ad;
                float ex = lrelu_exp(e);
                den += ex;
                acc += ex * __ldg(&Hm[s * 16 + c]);
            }
        }
    }
    acc += __shfl_xor_sync(0xffffffffu, acc, 16);
    den += __shfl_xor_sync(0xffffffffu, den, 16);
    if (lane < 16) g_acc[n * 16 + lane] = acc / (den + 1e-16f);
}

// ---------------- epilogue layer 3: bias + BN + ReLU + fc1 + ReLU + fc2 ----------------
__global__ void ep3(const float* __restrict__ b3, const float* __restrict__ gg,
                    const float* __restrict__ bb, const float* __restrict__ mm,
                    const float* __restrict__ vv, const float* __restrict__ fw1,
                    const float* __restrict__ fb1, const float* __restrict__ fw2,
                    const float* __restrict__ fb2, float* __restrict__ out) {
    int n = blockIdx.x * blockDim.x + threadIdx.x;
    if (n >= NN) return;
    float t[16];
#pragma unroll
    for (int c = 0; c < 16; c++) {
        float y = (g_acc[n * 16 + c] + __ldg(&b3[c]) - __ldg(&mm[c])) *
                      rsqrtf(__ldg(&vv[c]) + 1e-5f) * __ldg(&gg[c]) +
                  __ldg(&bb[c]);
        t[c] = fmaxf(y, 0.f);
    }
    float o = __ldg(&fb2[0]);
#pragma unroll
    for (int oo = 0; oo < 8; oo++) {
        float z = __ldg(&fb1[oo]);
#pragma unroll
        for (int c = 0; c < 16; c++) z += t[c] * __ldg(&fw1[c * 8 + oo]);
        z = fmaxf(z, 0.f);
        o += z * __ldg(&fw2[oo]);
    }
    out[n] = o;
}

// ---------------- launch ----------------
extern "C" void kernel_launch(void* const* d_in, const int* in_sizes, int n_in,
                              void* d_out, int out_size) {
    const float* x = (const float*)d_in[0];
    const int* ei = (const int*)d_in[1];
    const float* W1 = (const float*)d_in[2];
    const float* as1 = (const float*)d_in[3];
    const float* ad1 = (const float*)d_in[4];
    const float* b1 = (const float*)d_in[5];
    const float* g1 = (const float*)d_in[6];
    const float* bb1 = (const float*)d_in[7];
    const float* m1 = (const float*)d_in[8];
    const float* v1 = (const float*)d_in[9];
    const float* W2 = (const float*)d_in[10];
    const float* as2 = (const float*)d_in[11];
    const float* ad2 = (const float*)d_in[12];
    const float* b2 = (const float*)d_in[13];
    const float* g2 = (const float*)d_in[14];
    const float* bb2 = (const float*)d_in[15];
    const float* m2 = (const float*)d_in[16];
    const float* v2 = (const float*)d_in[17];
    const float* W3 = (const float*)d_in[18];
    const float* as3 = (const float*)d_in[19];
    const float* ad3 = (const float*)d_in[20];
    const float* b3 = (const float*)d_in[21];
    const float* g3 = (const float*)d_in[22];
    const float* bb3 = (const float*)d_in[23];
    const float* m3 = (const float*)d_in[24];
    const float* v3 = (const float*)d_in[25];
    const float* fw1 = (const float*)d_in[26];
    const float* fb1 = (const float*)d_in[27];
    const float* fw2 = (const float*)d_in[28];
    const float* fb2 = (const float*)d_in[29];
    float* out = (float*)d_out;

    float* ph = nullptr;
    float* px2 = nullptr;
    int* pdeg = nullptr;
    cudaGetSymbolAddress((void**)&ph, g_h);
    cudaGetSymbolAddress((void**)&px2, g_x2);
    cudaGetSymbolAddress((void**)&pdeg, g_deg);

    const int TB = 256;
    int nblk = (NN + TB - 1) / TB;
    int eblk = (ETOT + TB - 1) / TB;
    int aggblk = (NN * 32 + TB - 1) / TB;   // warp per node

    // ---- CSR build (reused by all 3 layers) ----
    cudaMemsetAsync(pdeg, 0, NN * sizeof(int));
    hist_kernel<<<eblk, TB>>>(ei);
    scan_kernel<<<1, 1024>>>();
    scatter_kernel<<<eblk, TB>>>(ei);

    // ---- Layer 1 ----
    gemm_kernel<128, 64><<<(NN + 15) / 16, TB>>>(x, W1, ph);
    al_kernel<4, 16><<<nblk, TB>>>(ph, as1, ad1);
    agg64<<<aggblk, TB>>>(ph, b1, g1, bb1, m1, v1, px2);

    // ---- Layer 2 ----
    gemm_kernel<64, 64><<<(NN + 15) / 16, TB>>>(px2, W2, ph);
    al_kernel<4, 16><<<nblk, TB>>>(ph, as2, ad2);
    agg64<<<aggblk, TB>>>(ph, b2, g2, bb2, m2, v2, px2);

    // ---- Layer 3 ----
    gemm_kernel<64, 16><<<(NN + 63) / 64, TB>>>(px2, W3, ph);
    al_kernel<1, 16><<<nblk, TB>>>(ph, as3, ad3);
    agg16<<<aggblk, TB>>>(ph);
    ep3<<<nblk, TB>>>(b3, g3, bb3, m3, v3, fw1, fb1, fw2, fb2, out);
}

// round 5
// speedup vs baseline: 1.5499x; 1.5168x over previous
#include <cuda_runtime.h>
#include <math.h>

#define NN 50000
#define EE 1600000
#define ETOT (EE + NN)

// ---------------- scratch ----------------
__device__ float g_h[NN * 64];
__device__ float g_x2[NN * 64];
__device__ float g_als[NN * 4];
__device__ float g_ald[NN * 4];
__device__ float g_acc[NN * 16];
__device__ int   g_deg[NN];
__device__ int   g_off[NN + 1];
__device__ int   g_cur[NN];
__device__ int   g_csr[ETOT];

// ================= CSR build =================
__global__ void hist_kernel(const int* __restrict__ ei) {
    int e = blockIdx.x * blockDim.x + threadIdx.x;
    if (e >= ETOT) return;
    int d = (e < EE) ? ei[EE + e] : (e - EE);
    atomicAdd(&g_deg[d], 1);
}

__global__ void scan_kernel() {
    __shared__ int partial[1024];
    int t = threadIdx.x;
    const int C = (NN + 1023) / 1024;
    int b0 = t * C;
    int b1 = min(b0 + C, NN);
    int sum = 0;
    for (int i = b0; i < b1; i++) sum += g_deg[i];
    partial[t] = sum;
    __syncthreads();
    for (int off = 1; off < 1024; off <<= 1) {
        int v = (t >= off) ? partial[t - off] : 0;
        __syncthreads();
        partial[t] += v;
        __syncthreads();
    }
    int run = (t == 0) ? 0 : partial[t - 1];
    for (int i = b0; i < b1; i++) {
        g_off[i] = run;
        g_cur[i] = run;
        run += g_deg[i];
    }
    if (t == 1023) g_off[NN] = run;
}

__global__ void scatter_kernel(const int* __restrict__ ei) {
    int e = blockIdx.x * blockDim.x + threadIdx.x;
    if (e >= ETOT) return;
    int s, d;
    if (e < EE) { s = ei[e]; d = ei[EE + e]; } else { s = e - EE; d = s; }
    int pos = atomicAdd(&g_cur[d], 1);
    g_csr[pos] = s;
}

// ---------------- GEMM 64-wide: 4x4 register tiling ----------------
template <int IN>
__global__ void __launch_bounds__(256)
gemm64(const float* __restrict__ X, const float* __restrict__ W,
       float* __restrict__ Hout) {
    constexpr int KT = 32;
    __shared__ float sW[KT][64];
    __shared__ float sX[64][KT + 1];
    int t = threadIdx.x;
    int tx = t & 15, ty = t >> 4;
    int row0 = blockIdx.x * 64;
    float acc[4][4];
#pragma unroll
    for (int r = 0; r < 4; r++)
#pragma unroll
        for (int c = 0; c < 4; c++) acc[r][c] = 0.f;

    for (int kt = 0; kt < IN; kt += KT) {
        for (int i = t; i < KT * 16; i += 256) {
            int kk = i >> 4;
            int c4 = (i & 15) << 2;
            *(float4*)&sW[kk][c4] = *(const float4*)&W[(kt + kk) * 64 + c4];
        }
        for (int i = t; i < 64 * (KT / 4); i += 256) {
            int r = i >> 3;
            int k4 = (i & 7) << 2;
            int gr = row0 + r;
            float4 v = (gr < NN) ? *(const float4*)&X[gr * IN + kt + k4]
                                 : make_float4(0.f, 0.f, 0.f, 0.f);
            sX[r][k4] = v.x; sX[r][k4 + 1] = v.y;
            sX[r][k4 + 2] = v.z; sX[r][k4 + 3] = v.w;
        }
        __syncthreads();
#pragma unroll
        for (int k = 0; k < KT; k++) {
            float4 w4 = *(float4*)&sW[k][tx * 4];
            float x0 = sX[ty * 4 + 0][k];
            float x1 = sX[ty * 4 + 1][k];
            float x2 = sX[ty * 4 + 2][k];
            float x3 = sX[ty * 4 + 3][k];
            acc[0][0] += x0 * w4.x; acc[0][1] += x0 * w4.y; acc[0][2] += x0 * w4.z; acc[0][3] += x0 * w4.w;
            acc[1][0] += x1 * w4.x; acc[1][1] += x1 * w4.y; acc[1][2] += x1 * w4.z; acc[1][3] += x1 * w4.w;
            acc[2][0] += x2 * w4.x; acc[2][1] += x2 * w4.y; acc[2][2] += x2 * w4.z; acc[2][3] += x2 * w4.w;
            acc[3][0] += x3 * w4.x; acc[3][1] += x3 * w4.y; acc[3][2] += x3 * w4.z; acc[3][3] += x3 * w4.w;
        }
        __syncthreads();
    }
#pragma unroll
    for (int r = 0; r < 4; r++) {
        int gr = row0 + ty * 4 + r;
        if (gr < NN) {
            float4 o = make_float4(acc[r][0], acc[r][1], acc[r][2], acc[r][3]);
            *(float4*)&Hout[gr * 64 + tx * 4] = o;
        }
    }
}

// ---------------- GEMM generic (layer 3, OUT=16) ----------------
template <int IN, int OUT>
__global__ void gemm_kernel(const float* __restrict__ X, const float* __restrict__ W,
                            float* __restrict__ Hout) {
    constexpr int RY = 256 / OUT;
    constexpr int RPT = 4;
    constexpr int RB = RY * RPT;
    __shared__ float sW[IN * OUT];
    __shared__ float sX[RB * IN];
    int t = threadIdx.x;
    int tx = t % OUT, ty = t / OUT;
    int row0 = blockIdx.x * RB;

    for (int i = t; i < IN * OUT; i += 256) sW[i] = W[i];
    for (int i = t; i < RB * IN; i += 256) {
        int r = row0 + i / IN;
        sX[i] = (r < NN) ? X[r * IN + (i % IN)] : 0.f;
    }
    __syncthreads();

    float acc[RPT];
#pragma unroll
    for (int rr = 0; rr < RPT; rr++) acc[rr] = 0.f;
    const float* xs = &sX[ty * RPT * IN];
    for (int k = 0; k < IN; k++) {
        float wv = sW[k * OUT + tx];
#pragma unroll
        for (int rr = 0; rr < RPT; rr++) acc[rr] += xs[rr * IN + k] * wv;
    }
#pragma unroll
    for (int rr = 0; rr < RPT; rr++) {
        int r = row0 + ty * RPT + rr;
        if (r < NN) Hout[r * OUT + tx] = acc[rr];
    }
}

// ---------------- per-node attention logits ----------------
template <int H, int C>
__global__ void al_kernel(const float* __restrict__ Hm, const float* __restrict__ a_s,
                          const float* __restrict__ a_d) {
    int n = blockIdx.x * blockDim.x + threadIdx.x;
    if (n >= NN) return;
#pragma unroll
    for (int h = 0; h < H; h++) {
        float s = 0.f, d = 0.f;
#pragma unroll
        for (int c4 = 0; c4 < C; c4 += 4) {
            float4 hv = *(const float4*)&Hm[n * H * C + h * C + c4];
            float4 asv = *(const float4*)&a_s[h * C + c4];
            float4 adv = *(const float4*)&a_d[h * C + c4];
            s += hv.x * asv.x + hv.y * asv.y + hv.z * asv.z + hv.w * asv.w;
            d += hv.x * adv.x + hv.y * adv.y + hv.z * adv.z + hv.w * adv.w;
        }
        g_als[n * H + h] = s;
        g_ald[n * H + h] = d;
    }
}

__device__ __forceinline__ float lrelu_exp(float v) {
    v = (v > 0.f) ? v : 0.2f * v;
    return __expf(v);
}

// ============ fused gather-aggregation, 64-wide (layers 1 & 2) ============
// warp per dst node. Batch of 32 edges: lane precomputes ex[0..3] for ITS edge,
// stages (s, ex[4]) in smem; inner loop is column-parallel reading via LDS.
__global__ void __launch_bounds__(256)
agg64(const float* __restrict__ Hm, const float* __restrict__ b,
      const float* __restrict__ gg, const float* __restrict__ bb,
      const float* __restrict__ mm, const float* __restrict__ vv,
      float* __restrict__ xnext) {
    __shared__ float sh_ex[8][4][32];
    __shared__ int sh_s[8][32];
    int w = threadIdx.x >> 5;
    int lane = threadIdx.x & 31;
    int n = (blockIdx.x * blockDim.x + threadIdx.x) >> 5;
    if (n >= NN) return;
    int c0 = lane, c1 = lane + 32;
    int h0 = lane >> 4, h1 = 2 + (lane >> 4);
    float4 ad4 = *(const float4*)&g_ald[n * 4];
    float acc0 = 0.f, acc1 = 0.f, den0 = 0.f, den1 = 0.f;
    int beg = g_off[n], end = g_off[n + 1];
    for (int base = beg; base < end; base += 32) {
        int idx = base + lane;
        bool valid = idx < end;
        int s = valid ? g_csr[idx] : 0;
        float4 as4 = *(const float4*)&g_als[s * 4];
        float e0 = valid ? lrelu_exp(as4.x + ad4.x) : 0.f;
        float e1 = valid ? lrelu_exp(as4.y + ad4.y) : 0.f;
        float e2 = valid ? lrelu_exp(as4.z + ad4.z) : 0.f;
        float e3 = valid ? lrelu_exp(as4.w + ad4.w) : 0.f;
        __syncwarp();
        sh_s[w][lane] = s;
        sh_ex[w][0][lane] = e0;
        sh_ex[w][1][lane] = e1;
        sh_ex[w][2][lane] = e2;
        sh_ex[w][3][lane] = e3;
        __syncwarp();
        int nk8 = (min(32, end - base) + 7) & ~7;
        for (int j0 = 0; j0 < nk8; j0 += 8) {
#pragma unroll
            for (int jj = 0; jj < 8; jj++) {
                int j = j0 + jj;
                int sj = sh_s[w][j];
                float ex0 = sh_ex[w][h0][j];
                float ex1 = sh_ex[w][h1][j];
                float hv0 = __ldg(&Hm[sj * 64 + c0]);
                float hv1 = __ldg(&Hm[sj * 64 + c1]);
                acc0 += ex0 * hv0;
                acc1 += ex1 * hv1;
                den0 += ex0;
                den1 += ex1;
            }
        }
    }
    float r0 = acc0 / (den0 + 1e-16f);
    float r1 = acc1 / (den1 + 1e-16f);
    float y0 = (r0 + __ldg(&b[c0]) - __ldg(&mm[c0])) * rsqrtf(__ldg(&vv[c0]) + 1e-5f) *
                   __ldg(&gg[c0]) + __ldg(&bb[c0]);
    float y1 = (r1 + __ldg(&b[c1]) - __ldg(&mm[c1])) * rsqrtf(__ldg(&vv[c1]) + 1e-5f) *
                   __ldg(&gg[c1]) + __ldg(&bb[c1]);
    xnext[n * 64 + c0] = fmaxf(y0, 0.f);
    xnext[n * 64 + c1] = fmaxf(y1, 0.f);
}

// ============ fused gather-aggregation, 16-wide (layer 3) ============
// warp per dst node; two halves process alternate edges (padded, ex=0).
__global__ void __launch_bounds__(256)
agg16(const float* __restrict__ Hm) {
    __shared__ float sh_ex[8][32];
    __shared__ int sh_s[8][32];
    int w = threadIdx.x >> 5;
    int lane = threadIdx.x & 31;
    int n = (blockIdx.x * blockDim.x + threadIdx.x) >> 5;
    if (n >= NN) return;
    int c = lane & 15;
    int half = lane >> 4;
    float ad = g_ald[n];
    float acc = 0.f, den = 0.f;
    int beg = g_off[n], end = g_off[n + 1];
    for (int base = beg; base < end; base += 32) {
        int idx = base + lane;
        bool valid = idx < end;
        int s = valid ? g_csr[idx] : 0;
        float ex = valid ? lrelu_exp(__ldg(&g_als[s]) + ad) : 0.f;
        __syncwarp();
        sh_s[w][lane] = s;
        sh_ex[w][lane] = ex;
        __syncwarp();
        int nk2 = (min(32, end - base) + 1) & ~1;
        for (int j0 = 0; j0 < nk2; j0 += 8) {
#pragma unroll
            for (int jj = 0; jj < 8; jj += 2) {
                int j = j0 + jj + half;
                if (j0 + jj < nk2) {
                    int sj = sh_s[w][j];
                    float exj = sh_ex[w][j];
                    den += exj;
                    acc += exj * __ldg(&Hm[sj * 16 + c]);
                }
            }
        }
    }
    acc += __shfl_xor_sync(0xffffffffu, acc, 16);
    den += __shfl_xor_sync(0xffffffffu, den, 16);
    if (lane < 16) g_acc[n * 16 + lane] = acc / (den + 1e-16f);
}

// ---------------- epilogue layer 3 ----------------
__global__ void ep3(const float* __restrict__ b3, const float* __restrict__ gg,
                    const float* __restrict__ bb, const float* __restrict__ mm,
                    const float* __restrict__ vv, const float* __restrict__ fw1,
                    const float* __restrict__ fb1, const float* __restrict__ fw2,
                    const float* __restrict__ fb2, float* __restrict__ out) {
    int n = blockIdx.x * blockDim.x + threadIdx.x;
    if (n >= NN) return;
    float t[16];
#pragma unroll
    for (int c = 0; c < 16; c++) {
        float y = (g_acc[n * 16 + c] + __ldg(&b3[c]) - __ldg(&mm[c])) *
                      rsqrtf(__ldg(&vv[c]) + 1e-5f) * __ldg(&gg[c]) +
                  __ldg(&bb[c]);
        t[c] = fmaxf(y, 0.f);
    }
    float o = __ldg(&fb2[0]);
#pragma unroll
    for (int oo = 0; oo < 8; oo++) {
        float z = __ldg(&fb1[oo]);
#pragma unroll
        for (int c = 0; c < 16; c++) z += t[c] * __ldg(&fw1[c * 8 + oo]);
        z = fmaxf(z, 0.f);
        o += z * __ldg(&fw2[oo]);
    }
    out[n] = o;
}

// ---------------- launch ----------------
extern "C" void kernel_launch(void* const* d_in, const int* in_sizes, int n_in,
                              void* d_out, int out_size) {
    const float* x = (const float*)d_in[0];
    const int* ei = (const int*)d_in[1];
    const float* W1 = (const float*)d_in[2];
    const float* as1 = (const float*)d_in[3];
    const float* ad1 = (const float*)d_in[4];
    const float* b1 = (const float*)d_in[5];
    const float* g1 = (const float*)d_in[6];
    const float* bb1 = (const float*)d_in[7];
    const float* m1 = (const float*)d_in[8];
    const float* v1 = (const float*)d_in[9];
    const float* W2 = (const float*)d_in[10];
    const float* as2 = (const float*)d_in[11];
    const float* ad2 = (const float*)d_in[12];
    const float* b2 = (const float*)d_in[13];
    const float* g2 = (const float*)d_in[14];
    const float* bb2 = (const float*)d_in[15];
    const float* m2 = (const float*)d_in[16];
    const float* v2 = (const float*)d_in[17];
    const float* W3 = (const float*)d_in[18];
    const float* as3 = (const float*)d_in[19];
    const float* ad3 = (const float*)d_in[20];
    const float* b3 = (const float*)d_in[21];
    const float* g3 = (const float*)d_in[22];
    const float* bb3 = (const float*)d_in[23];
    const float* m3 = (const float*)d_in[24];
    const float* v3 = (const float*)d_in[25];
    const float* fw1 = (const float*)d_in[26];
    const float* fb1 = (const float*)d_in[27];
    const float* fw2 = (const float*)d_in[28];
    const float* fb2 = (const float*)d_in[29];
    float* out = (float*)d_out;

    float* ph = nullptr;
    float* px2 = nullptr;
    int* pdeg = nullptr;
    cudaGetSymbolAddress((void**)&ph, g_h);
    cudaGetSymbolAddress((void**)&px2, g_x2);
    cudaGetSymbolAddress((void**)&pdeg, g_deg);

    const int TB = 256;
    int nblk = (NN + TB - 1) / TB;
    int eblk = (ETOT + TB - 1) / TB;
    int aggblk = (NN * 32 + TB - 1) / TB;
    int g64blk = (NN + 63) / 64;

    // ---- CSR build ----
    cudaMemsetAsync(pdeg, 0, NN * sizeof(int));
    hist_kernel<<<eblk, TB>>>(ei);
    scan_kernel<<<1, 1024>>>();
    scatter_kernel<<<eblk, TB>>>(ei);

    // ---- Layer 1 ----
    gemm64<128><<<g64blk, TB>>>(x, W1, ph);
    al_kernel<4, 16><<<nblk, TB>>>(ph, as1, ad1);
    agg64<<<aggblk, TB>>>(ph, b1, g1, bb1, m1, v1, px2);

    // ---- Layer 2 ----
    gemm64<64><<<g64blk, TB>>>(px2, W2, ph);
    al_kernel<4, 16><<<nblk, TB>>>(ph, as2, ad2);
    agg64<<<aggblk, TB>>>(ph, b2, g2, bb2, m2, v2, px2);

    // ---- Layer 3 ----
    gemm_kernel<64, 16><<<(NN + 63) / 64, TB>>>(px2, W3, ph);
    al_kernel<1, 16><<<nblk, TB>>>(ph, as3, ad3);
    agg16<<<aggblk, TB>>>(ph);
    ep3<<<nblk, TB>>>(b3, g3, bb3, m3, v3, fw1, fb1, fw2, fb2, out);
}

// round 6
// speedup vs baseline: 1.5846x; 1.0224x over previous
#include <cuda_runtime.h>
#include <cuda_fp16.h>
#include <math.h>

#define NN 50000
#define EE 1600000
#define ETOT (EE + NN)

// ---------------- scratch ----------------
__device__ float  g_h[NN * 16];      // layer-3 fp32 h (for al_kernel)
__device__ __half g_h16[NN * 64];    // fp16 h for gather (all layers)
__device__ float  g_x2[NN * 64];
__device__ float  g_als[NN * 4];
__device__ float  g_ald[NN * 4];
__device__ float  g_acc[NN * 16];
__device__ int    g_deg[NN];
__device__ int    g_off[NN + 1];
__device__ int    g_cur[NN];
__device__ int    g_csr[ETOT];

// ================= CSR build =================
__global__ void hist_kernel(const int* __restrict__ ei) {
    int e = blockIdx.x * blockDim.x + threadIdx.x;
    if (e >= ETOT) return;
    int d = (e < EE) ? ei[EE + e] : (e - EE);
    atomicAdd(&g_deg[d], 1);
}

__global__ void scan_kernel() {
    __shared__ int partial[1024];
    int t = threadIdx.x;
    const int C = (NN + 1023) / 1024;
    int b0 = t * C;
    int b1 = min(b0 + C, NN);
    int sum = 0;
    for (int i = b0; i < b1; i++) sum += g_deg[i];
    partial[t] = sum;
    __syncthreads();
    for (int off = 1; off < 1024; off <<= 1) {
        int v = (t >= off) ? partial[t - off] : 0;
        __syncthreads();
        partial[t] += v;
        __syncthreads();
    }
    int run = (t == 0) ? 0 : partial[t - 1];
    for (int i = b0; i < b1; i++) {
        g_off[i] = run;
        g_cur[i] = run;
        run += g_deg[i];
    }
    if (t == 1023) g_off[NN] = run;
}

__global__ void scatter_kernel(const int* __restrict__ ei) {
    int e = blockIdx.x * blockDim.x + threadIdx.x;
    if (e >= ETOT) return;
    int s, d;
    if (e < EE) { s = ei[e]; d = ei[EE + e]; } else { s = e - EE; d = s; }
    int pos = atomicAdd(&g_cur[d], 1);
    g_csr[pos] = s;
}

// ---------------- GEMM 64-wide + fused attention logits + fp16 h store ------
// 4x4 register tile; epilogue computes als/ald (4-lane shfl reduce per head)
// and stores h as half2. No fp32 h is written at all.
template <int IN>
__global__ void __launch_bounds__(256)
gemm64(const float* __restrict__ X, const float* __restrict__ W,
       const float* __restrict__ a_s, const float* __restrict__ a_d) {
    constexpr int KT = 32;
    __shared__ float sW[KT][64];
    __shared__ float sX[64][KT + 1];
    int t = threadIdx.x;
    int tx = t & 15, ty = t >> 4;
    int row0 = blockIdx.x * 64;
    float acc[4][4];
#pragma unroll
    for (int r = 0; r < 4; r++)
#pragma unroll
        for (int c = 0; c < 4; c++) acc[r][c] = 0.f;

    for (int kt = 0; kt < IN; kt += KT) {
        for (int i = t; i < KT * 16; i += 256) {
            int kk = i >> 4;
            int c4 = (i & 15) << 2;
            *(float4*)&sW[kk][c4] = *(const float4*)&W[(kt + kk) * 64 + c4];
        }
        for (int i = t; i < 64 * (KT / 4); i += 256) {
            int r = i >> 3;
            int k4 = (i & 7) << 2;
            int gr = row0 + r;
            float4 v = (gr < NN) ? *(const float4*)&X[gr * IN + kt + k4]
                                 : make_float4(0.f, 0.f, 0.f, 0.f);
            sX[r][k4] = v.x; sX[r][k4 + 1] = v.y;
            sX[r][k4 + 2] = v.z; sX[r][k4 + 3] = v.w;
        }
        __syncthreads();
#pragma unroll
        for (int k = 0; k < KT; k++) {
            float4 w4 = *(float4*)&sW[k][tx * 4];
            float x0 = sX[ty * 4 + 0][k];
            float x1 = sX[ty * 4 + 1][k];
            float x2 = sX[ty * 4 + 2][k];
            float x3 = sX[ty * 4 + 3][k];
            acc[0][0] += x0 * w4.x; acc[0][1] += x0 * w4.y; acc[0][2] += x0 * w4.z; acc[0][3] += x0 * w4.w;
            acc[1][0] += x1 * w4.x; acc[1][1] += x1 * w4.y; acc[1][2] += x1 * w4.z; acc[1][3] += x1 * w4.w;
            acc[2][0] += x2 * w4.x; acc[2][1] += x2 * w4.y; acc[2][2] += x2 * w4.z; acc[2][3] += x2 * w4.w;
            acc[3][0] += x3 * w4.x; acc[3][1] += x3 * w4.y; acc[3][2] += x3 * w4.z; acc[3][3] += x3 * w4.w;
        }
        __syncthreads();
    }

    // fused attention-logit epilogue: head h = tx>>2, cols (tx&3)*4 .. +3 of it
    int h = tx >> 2;
    float4 asv = *(const float4*)&a_s[h * 16 + (tx & 3) * 4];
    float4 adv = *(const float4*)&a_d[h * 16 + (tx & 3) * 4];
    __half2* h2out = (__half2*)g_h16;
#pragma unroll
    for (int r = 0; r < 4; r++) {
        int gr = row0 + ty * 4 + r;
        float ps = acc[r][0] * asv.x + acc[r][1] * asv.y + acc[r][2] * asv.z + acc[r][3] * asv.w;
        float pd = acc[r][0] * adv.x + acc[r][1] * adv.y + acc[r][2] * adv.z + acc[r][3] * adv.w;
        ps += __shfl_xor_sync(0xffffffffu, ps, 1);
        ps += __shfl_xor_sync(0xffffffffu, ps, 2);
        pd += __shfl_xor_sync(0xffffffffu, pd, 1);
        pd += __shfl_xor_sync(0xffffffffu, pd, 2);
        if (gr < NN) {
            h2out[(gr * 64 + tx * 4) >> 1] = __floats2half2_rn(acc[r][0], acc[r][1]);
            h2out[((gr * 64 + tx * 4) >> 1) + 1] = __floats2half2_rn(acc[r][2], acc[r][3]);
            if ((tx & 3) == 0) {
                g_als[gr * 4 + h] = ps;
                g_ald[gr * 4 + h] = pd;
            }
        }
    }
}

// ---------------- GEMM layer 3 (64->16): fp32 + fp16 out ----------------
__global__ void gemm16(const float* __restrict__ X, const float* __restrict__ W,
                       float* __restrict__ Hout) {
    constexpr int IN = 64, OUT = 16;
    constexpr int RB = 64;
    __shared__ float sW[IN * OUT];
    __shared__ float sX[RB * IN];
    int t = threadIdx.x;
    int tx = t % OUT, ty = t / OUT;
    int row0 = blockIdx.x * RB;

    for (int i = t; i < IN * OUT; i += 256) sW[i] = W[i];
    for (int i = t; i < RB * IN; i += 256) {
        int r = row0 + i / IN;
        sX[i] = (r < NN) ? X[r * IN + (i % IN)] : 0.f;
    }
    __syncthreads();

    float acc[4];
#pragma unroll
    for (int rr = 0; rr < 4; rr++) acc[rr] = 0.f;
    const float* xs = &sX[ty * 4 * IN];
    for (int k = 0; k < IN; k++) {
        float wv = sW[k * OUT + tx];
#pragma unroll
        for (int rr = 0; rr < 4; rr++) acc[rr] += xs[rr * IN + k] * wv;
    }
#pragma unroll
    for (int rr = 0; rr < 4; rr++) {
        int r = row0 + ty * 4 + rr;
        if (r < NN) {
            Hout[r * OUT + tx] = acc[rr];
            g_h16[r * OUT + tx] = __float2half_rn(acc[rr]);
        }
    }
}

// ---------------- layer-3 attention logits ----------------
__global__ void al1(const float* __restrict__ Hm, const float* __restrict__ a_s,
                    const float* __restrict__ a_d) {
    int n = blockIdx.x * blockDim.x + threadIdx.x;
    if (n >= NN) return;
    float s = 0.f, d = 0.f;
#pragma unroll
    for (int c4 = 0; c4 < 16; c4 += 4) {
        float4 hv = *(const float4*)&Hm[n * 16 + c4];
        float4 asv = *(const float4*)&a_s[c4];
        float4 adv = *(const float4*)&a_d[c4];
        s += hv.x * asv.x + hv.y * asv.y + hv.z * asv.z + hv.w * asv.w;
        d += hv.x * adv.x + hv.y * adv.y + hv.z * adv.z + hv.w * adv.w;
    }
    g_als[n] = s;
    g_ald[n] = d;
}

__device__ __forceinline__ float lrelu_exp(float v) {
    v = (v > 0.f) ? v : 0.2f * v;
    return __expf(v);
}

// ============ fused gather-aggregation, 64-wide (layers 1 & 2) ============
// warp per dst node; lane owns half2 cols (2*lane, 2*lane+1), head = lane>>3.
__global__ void __launch_bounds__(256)
agg64(const float* __restrict__ b,
      const float* __restrict__ gg, const float* __restrict__ bb,
      const float* __restrict__ mm, const float* __restrict__ vv,
      float* __restrict__ xnext) {
    __shared__ float sh_ex[8][4][33];
    __shared__ int sh_s[8][32];
    int w = threadIdx.x >> 5;
    int lane = threadIdx.x & 31;
    int n = (blockIdx.x * blockDim.x + threadIdx.x) >> 5;
    if (n >= NN) return;
    int c0 = 2 * lane;
    int h = lane >> 3;
    float4 ad4 = *(const float4*)&g_ald[n * 4];
    float accx = 0.f, accy = 0.f, den = 0.f;
    const __half2* ph2 = (const __half2*)g_h16;
    int beg = g_off[n], end = g_off[n + 1];
    for (int base = beg; base < end; base += 32) {
        int idx = base + lane;
        bool valid = idx < end;
        int s = valid ? g_csr[idx] : 0;
        float4 as4 = *(const float4*)&g_als[s * 4];
        float e0 = valid ? lrelu_exp(as4.x + ad4.x) : 0.f;
        float e1 = valid ? lrelu_exp(as4.y + ad4.y) : 0.f;
        float e2 = valid ? lrelu_exp(as4.z + ad4.z) : 0.f;
        float e3 = valid ? lrelu_exp(as4.w + ad4.w) : 0.f;
        __syncwarp();
        sh_s[w][lane] = s;
        sh_ex[w][0][lane] = e0;
        sh_ex[w][1][lane] = e1;
        sh_ex[w][2][lane] = e2;
        sh_ex[w][3][lane] = e3;
        __syncwarp();
        int nk8 = (min(32, end - base) + 7) & ~7;
        for (int j0 = 0; j0 < nk8; j0 += 8) {
#pragma unroll
            for (int jj = 0; jj < 8; jj++) {
                int j = j0 + jj;
                int sj = sh_s[w][j];
                float ex = sh_ex[w][h][j];
                float2 f = __half22float2(__ldg(&ph2[sj * 32 + lane]));
                accx += ex * f.x;
                accy += ex * f.y;
                den += ex;
            }
        }
    }
    float inv = 1.f / (den + 1e-16f);
    float r0 = accx * inv;
    float r1 = accy * inv;
    int c1 = c0 + 1;
    float y0 = (r0 + __ldg(&b[c0]) - __ldg(&mm[c0])) * rsqrtf(__ldg(&vv[c0]) + 1e-5f) *
                   __ldg(&gg[c0]) + __ldg(&bb[c0]);
    float y1 = (r1 + __ldg(&b[c1]) - __ldg(&mm[c1])) * rsqrtf(__ldg(&vv[c1]) + 1e-5f) *
                   __ldg(&gg[c1]) + __ldg(&bb[c1]);
    float2 o = make_float2(fmaxf(y0, 0.f), fmaxf(y1, 0.f));
    *(float2*)&xnext[n * 64 + c0] = o;
}

// ============ fused gather-aggregation, 16-wide (layer 3) ============
__global__ void __launch_bounds__(256)
agg16() {
    __shared__ float sh_ex[8][32];
    __shared__ int sh_s[8][32];
    int w = threadIdx.x >> 5;
    int lane = threadIdx.x & 31;
    int n = (blockIdx.x * blockDim.x + threadIdx.x) >> 5;
    if (n >= NN) return;
    int c = lane & 15;
    int half = lane >> 4;
    float ad = g_ald[n];
    float acc = 0.f, den = 0.f;
    int beg = g_off[n], end = g_off[n + 1];
    for (int base = beg; base < end; base += 32) {
        int idx = base + lane;
        bool valid = idx < end;
        int s = valid ? g_csr[idx] : 0;
        float ex = valid ? lrelu_exp(__ldg(&g_als[s]) + ad) : 0.f;
        __syncwarp();
        sh_s[w][lane] = s;
        sh_ex[w][lane] = ex;
        __syncwarp();
        int nk2 = (min(32, end - base) + 1) & ~1;
        for (int j0 = 0; j0 < nk2; j0 += 8) {
#pragma unroll
            for (int jj = 0; jj < 8; jj += 2) {
                int j = j0 + jj + half;
                if (j0 + jj < nk2) {
                    int sj = sh_s[w][j];
                    float exj = sh_ex[w][j];
                    den += exj;
                    acc += exj * __half2float(g_h16[sj * 16 + c]);
                }
            }
        }
    }
    acc += __shfl_xor_sync(0xffffffffu, acc, 16);
    den += __shfl_xor_sync(0xffffffffu, den, 16);
    if (lane < 16) g_acc[n * 16 + lane] = acc / (den + 1e-16f);
}

// ---------------- epilogue layer 3 ----------------
__global__ void ep3(const float* __restrict__ b3, const float* __restrict__ gg,
                    const float* __restrict__ bb, const float* __restrict__ mm,
                    const float* __restrict__ vv, const float* __restrict__ fw1,
                    const float* __restrict__ fb1, const float* __restrict__ fw2,
                    const float* __restrict__ fb2, float* __restrict__ out) {
    int n = blockIdx.x * blockDim.x + threadIdx.x;
    if (n >= NN) return;
    float t[16];
#pragma unroll
    for (int c = 0; c < 16; c++) {
        float y = (g_acc[n * 16 + c] + __ldg(&b3[c]) - __ldg(&mm[c])) *
                      rsqrtf(__ldg(&vv[c]) + 1e-5f) * __ldg(&gg[c]) +
                  __ldg(&bb[c]);
        t[c] = fmaxf(y, 0.f);
    }
    float o = __ldg(&fb2[0]);
#pragma unroll
    for (int oo = 0; oo < 8; oo++) {
        float z = __ldg(&fb1[oo]);
#pragma unroll
        for (int c = 0; c < 16; c++) z += t[c] * __ldg(&fw1[c * 8 + oo]);
        z = fmaxf(z, 0.f);
        o += z * __ldg(&fw2[oo]);
    }
    out[n] = o;
}

// ---------------- launch ----------------
extern "C" void kernel_launch(void* const* d_in, const int* in_sizes, int n_in,
                              void* d_out, int out_size) {
    const float* x = (const float*)d_in[0];
    const int* ei = (const int*)d_in[1];
    const float* W1 = (const float*)d_in[2];
    const float* as1 = (const float*)d_in[3];
    const float* ad1 = (const float*)d_in[4];
    const float* b1 = (const float*)d_in[5];
    const float* g1 = (const float*)d_in[6];
    const float* bb1 = (const float*)d_in[7];
    const float* m1 = (const float*)d_in[8];
    const float* v1 = (const float*)d_in[9];
    const float* W2 = (const float*)d_in[10];
    const float* as2 = (const float*)d_in[11];
    const float* ad2 = (const float*)d_in[12];
    const float* b2 = (const float*)d_in[13];
    const float* g2 = (const float*)d_in[14];
    const float* bb2 = (const float*)d_in[15];
    const float* m2 = (const float*)d_in[16];
    const float* v2 = (const float*)d_in[17];
    const float* W3 = (const float*)d_in[18];
    const float* as3 = (const float*)d_in[19];
    const float* ad3 = (const float*)d_in[20];
    const float* b3 = (const float*)d_in[21];
    const float* g3 = (const float*)d_in[22];
    const float* bb3 = (const float*)d_in[23];
    const float* m3 = (const float*)d_in[24];
    const float* v3 = (const float*)d_in[25];
    const float* fw1 = (const float*)d_in[26];
    const float* fb1 = (const float*)d_in[27];
    const float* fw2 = (const float*)d_in[28];
    const float* fb2 = (const float*)d_in[29];
    float* out = (float*)d_out;

    float* ph = nullptr;
    float* px2 = nullptr;
    int* pdeg = nullptr;
    cudaGetSymbolAddress((void**)&ph, g_h);
    cudaGetSymbolAddress((void**)&px2, g_x2);
    cudaGetSymbolAddress((void**)&pdeg, g_deg);

    const int TB = 256;
    int nblk = (NN + TB - 1) / TB;
    int eblk = (ETOT + TB - 1) / TB;
    int aggblk = (NN * 32 + TB - 1) / TB;
    int g64blk = (NN + 63) / 64;

    // ---- CSR build ----
    cudaMemsetAsync(pdeg, 0, NN * sizeof(int));
    hist_kernel<<<eblk, TB>>>(ei);
    scan_kernel<<<1, 1024>>>();
    scatter_kernel<<<eblk, TB>>>(ei);

    // ---- Layer 1 ----
    gemm64<128><<<g64blk, TB>>>(x, W1, as1, ad1);
    agg64<<<aggblk, TB>>>(b1, g1, bb1, m1, v1, px2);

    // ---- Layer 2 ----
    gemm64<64><<<g64blk, TB>>>(px2, W2, as2, ad2);
    agg64<<<aggblk, TB>>>(b2, g2, bb2, m2, v2, px2);

    // ---- Layer 3 ----
    gemm16<<<(NN + 63) / 64, TB>>>(px2, W3, ph);
    al1<<<nblk, TB>>>(ph, as3, ad3);
    agg16<<<aggblk, TB>>>();
    ep3<<<nblk, TB>>>(b3, g3, bb3, m3, v3, fw1, fb1, fw2, fb2, out);
}

// round 7
// speedup vs baseline: 1.6166x; 1.0202x over previous
#include <cuda_runtime.h>
#include <cuda_fp16.h>
#include <math.h>

#define NN 50000
#define EE 1600000
#define ETOT (EE + NN)

// ---------------- scratch ----------------
__device__ float  g_h[NN * 16];      // layer-3 fp32 h (for al1)
__device__ __half g_h16[NN * 64];    // fp16 h for gather (all layers)
__device__ float  g_x2[NN * 64];
__device__ float  g_als[NN * 4];
__device__ float  g_ald[NN * 4];
__device__ float  g_acc[NN * 16];
__device__ int    g_deg[NN];
__device__ int    g_off[NN + 1];
__device__ int    g_cur[NN];
__device__ int    g_csr[ETOT];

// ================= CSR build =================
__global__ void hist_kernel(const int* __restrict__ ei) {
    int e = blockIdx.x * blockDim.x + threadIdx.x;
    if (e >= ETOT) return;
    int d = (e < EE) ? ei[EE + e] : (e - EE);
    atomicAdd(&g_deg[d], 1);
}

__global__ void scan_kernel() {
    __shared__ int partial[1024];
    int t = threadIdx.x;
    const int C = (NN + 1023) / 1024;
    int b0 = t * C;
    int b1 = min(b0 + C, NN);
    int sum = 0;
    for (int i = b0; i < b1; i++) sum += g_deg[i];
    partial[t] = sum;
    __syncthreads();
    for (int off = 1; off < 1024; off <<= 1) {
        int v = (t >= off) ? partial[t - off] : 0;
        __syncthreads();
        partial[t] += v;
        __syncthreads();
    }
    int run = (t == 0) ? 0 : partial[t - 1];
    for (int i = b0; i < b1; i++) {
        g_off[i] = run;
        g_cur[i] = run;
        run += g_deg[i];
    }
    if (t == 1023) g_off[NN] = run;
}

__global__ void scatter_kernel(const int* __restrict__ ei) {
    int e = blockIdx.x * blockDim.x + threadIdx.x;
    if (e >= ETOT) return;
    int s, d;
    if (e < EE) { s = ei[e]; d = ei[EE + e]; } else { s = e - EE; d = s; }
    int pos = atomicAdd(&g_cur[d], 1);
    g_csr[pos] = s;
}

// ------- GEMM 64-wide, 128-row tile, transposed X smem, fused al + fp16 out ----
template <int IN>
__global__ void __launch_bounds__(256)
gemm64(const float* __restrict__ X, const float* __restrict__ W,
       const float* __restrict__ a_s, const float* __restrict__ a_d) {
    constexpr int KT = 32;
    constexpr int SXS = 132;              // stride (floats) for transposed X tile
    __shared__ float sW[KT][64];
    __shared__ float sX2[KT][SXS];
    int t = threadIdx.x;
    int tx = t & 15, ty = t >> 4;         // tx: col group (4 cols), ty: row group (8 rows)
    int row0 = blockIdx.x * 128;
    float acc[8][4];
#pragma unroll
    for (int r = 0; r < 8; r++)
#pragma unroll
        for (int c = 0; c < 4; c++) acc[r][c] = 0.f;

    for (int kt = 0; kt < IN; kt += KT) {
        // stage W [KT x 64]
#pragma unroll
        for (int i = t; i < KT * 16; i += 256) {
            int kk = i >> 4;
            int c4 = (i & 15) << 2;
            *(float4*)&sW[kk][c4] = *(const float4*)&W[(kt + kk) * 64 + c4];
        }
        // stage X transposed: sX2[k][r]
#pragma unroll
        for (int i = t; i < 128 * (KT / 4); i += 256) {
            int r = i >> 3;
            int k4 = (i & 7) << 2;
            int gr = row0 + r;
            float4 v = (gr < NN) ? *(const float4*)&X[gr * IN + kt + k4]
                                 : make_float4(0.f, 0.f, 0.f, 0.f);
            sX2[k4 + 0][r] = v.x;
            sX2[k4 + 1][r] = v.y;
            sX2[k4 + 2][r] = v.z;
            sX2[k4 + 3][r] = v.w;
        }
        __syncthreads();
#pragma unroll
        for (int k = 0; k < KT; k++) {
            float4 w4 = *(float4*)&sW[k][tx * 4];
            float4 xa = *(float4*)&sX2[k][ty * 8];
            float4 xb = *(float4*)&sX2[k][ty * 8 + 4];
            float xr[8] = {xa.x, xa.y, xa.z, xa.w, xb.x, xb.y, xb.z, xb.w};
#pragma unroll
            for (int r = 0; r < 8; r++) {
                acc[r][0] += xr[r] * w4.x;
                acc[r][1] += xr[r] * w4.y;
                acc[r][2] += xr[r] * w4.z;
                acc[r][3] += xr[r] * w4.w;
            }
        }
        __syncthreads();
    }

    // fused attention-logit epilogue: head h = tx>>2, this thread covers 4 cols of it
    int h = tx >> 2;
    float4 asv = *(const float4*)&a_s[h * 16 + (tx & 3) * 4];
    float4 adv = *(const float4*)&a_d[h * 16 + (tx & 3) * 4];
    __half2* h2out = (__half2*)g_h16;
#pragma unroll
    for (int r = 0; r < 8; r++) {
        int gr = row0 + ty * 8 + r;
        float ps = acc[r][0] * asv.x + acc[r][1] * asv.y + acc[r][2] * asv.z + acc[r][3] * asv.w;
        float pd = acc[r][0] * adv.x + acc[r][1] * adv.y + acc[r][2] * adv.z + acc[r][3] * adv.w;
        ps += __shfl_xor_sync(0xffffffffu, ps, 1);
        ps += __shfl_xor_sync(0xffffffffu, ps, 2);
        pd += __shfl_xor_sync(0xffffffffu, pd, 1);
        pd += __shfl_xor_sync(0xffffffffu, pd, 2);
        if (gr < NN) {
            h2out[(gr * 64 + tx * 4) >> 1] = __floats2half2_rn(acc[r][0], acc[r][1]);
            h2out[((gr * 64 + tx * 4) >> 1) + 1] = __floats2half2_rn(acc[r][2], acc[r][3]);
            if ((tx & 3) == 0) {
                g_als[gr * 4 + h] = ps;
                g_ald[gr * 4 + h] = pd;
            }
        }
    }
}

// ---------------- GEMM layer 3 (64->16): fp32 + fp16 out ----------------
__global__ void gemm16(const float* __restrict__ X, const float* __restrict__ W,
                       float* __restrict__ Hout) {
    constexpr int IN = 64, OUT = 16;
    constexpr int RB = 64;
    __shared__ float sW[IN * OUT];
    __shared__ float sX[RB * IN];
    int t = threadIdx.x;
    int tx = t % OUT, ty = t / OUT;
    int row0 = blockIdx.x * RB;

    for (int i = t; i < IN * OUT; i += 256) sW[i] = W[i];
    for (int i = t; i < RB * IN; i += 256) {
        int r = row0 + i / IN;
        sX[i] = (r < NN) ? X[r * IN + (i % IN)] : 0.f;
    }
    __syncthreads();

    float acc[4];
#pragma unroll
    for (int rr = 0; rr < 4; rr++) acc[rr] = 0.f;
    const float* xs = &sX[ty * 4 * IN];
    for (int k = 0; k < IN; k++) {
        float wv = sW[k * OUT + tx];
#pragma unroll
        for (int rr = 0; rr < 4; rr++) acc[rr] += xs[rr * IN + k] * wv;
    }
#pragma unroll
    for (int rr = 0; rr < 4; rr++) {
        int r = row0 + ty * 4 + rr;
        if (r < NN) {
            Hout[r * OUT + tx] = acc[rr];
            g_h16[r * OUT + tx] = __float2half_rn(acc[rr]);
        }
    }
}

// ---------------- layer-3 attention logits ----------------
__global__ void al1(const float* __restrict__ Hm, const float* __restrict__ a_s,
                    const float* __restrict__ a_d) {
    int n = blockIdx.x * blockDim.x + threadIdx.x;
    if (n >= NN) return;
    float s = 0.f, d = 0.f;
#pragma unroll
    for (int c4 = 0; c4 < 16; c4 += 4) {
        float4 hv = *(const float4*)&Hm[n * 16 + c4];
        float4 asv = *(const float4*)&a_s[c4];
        float4 adv = *(const float4*)&a_d[c4];
        s += hv.x * asv.x + hv.y * asv.y + hv.z * asv.z + hv.w * asv.w;
        d += hv.x * adv.x + hv.y * adv.y + hv.z * adv.z + hv.w * adv.w;
    }
    g_als[n] = s;
    g_ald[n] = d;
}

__device__ __forceinline__ float lrelu_exp(float v) {
    v = (v > 0.f) ? v : 0.2f * v;
    return __expf(v);
}

// ============ fused gather-aggregation, 64-wide (layers 1 & 2) ============
// warp per dst node; lane owns half2 cols (2*lane, 2*lane+1), head = lane>>3.
// den computed via butterfly reduce in the precompute phase (not in hot loop).
__global__ void __launch_bounds__(256)
agg64(const float* __restrict__ b,
      const float* __restrict__ gg, const float* __restrict__ bb,
      const float* __restrict__ mm, const float* __restrict__ vv,
      float* __restrict__ xnext) {
    __shared__ float sh_ex[8][4][33];
    __shared__ int sh_s[8][32];
    int w = threadIdx.x >> 5;
    int lane = threadIdx.x & 31;
    int n = (blockIdx.x * blockDim.x + threadIdx.x) >> 5;
    if (n >= NN) return;
    int c0 = 2 * lane;
    int h = lane >> 3;
    float4 ad4 = *(const float4*)&g_ald[n * 4];
    float accx = 0.f, accy = 0.f, den = 0.f;
    const __half2* ph2 = (const __half2*)g_h16;
    int beg = g_off[n], end = g_off[n + 1];
    for (int base = beg; base < end; base += 32) {
        int idx = base + lane;
        bool valid = idx < end;
        int s = valid ? g_csr[idx] : 0;
        float4 as4 = *(const float4*)&g_als[s * 4];
        float e0 = valid ? lrelu_exp(as4.x + ad4.x) : 0.f;
        float e1 = valid ? lrelu_exp(as4.y + ad4.y) : 0.f;
        float e2 = valid ? lrelu_exp(as4.z + ad4.z) : 0.f;
        float e3 = valid ? lrelu_exp(as4.w + ad4.w) : 0.f;
        // butterfly-reduce per-head denominators across the 32-edge batch
        float d0 = e0, d1 = e1, d2 = e2, d3 = e3;
#pragma unroll
        for (int off = 16; off > 0; off >>= 1) {
            d0 += __shfl_xor_sync(0xffffffffu, d0, off);
            d1 += __shfl_xor_sync(0xffffffffu, d1, off);
            d2 += __shfl_xor_sync(0xffffffffu, d2, off);
            d3 += __shfl_xor_sync(0xffffffffu, d3, off);
        }
        den += (h == 0) ? d0 : (h == 1) ? d1 : (h == 2) ? d2 : d3;
        __syncwarp();
        sh_s[w][lane] = s;
        sh_ex[w][0][lane] = e0;
        sh_ex[w][1][lane] = e1;
        sh_ex[w][2][lane] = e2;
        sh_ex[w][3][lane] = e3;
        __syncwarp();
        int nk8 = (min(32, end - base) + 7) & ~7;
        for (int j0 = 0; j0 < nk8; j0 += 8) {
#pragma unroll
            for (int jj = 0; jj < 8; jj++) {
                int j = j0 + jj;
                int sj = sh_s[w][j];
                float ex = sh_ex[w][h][j];
                float2 f = __half22float2(__ldg(&ph2[sj * 32 + lane]));
                accx += ex * f.x;
                accy += ex * f.y;
            }
        }
    }
    float inv = 1.f / (den + 1e-16f);
    float r0 = accx * inv;
    float r1 = accy * inv;
    int c1 = c0 + 1;
    float y0 = (r0 + __ldg(&b[c0]) - __ldg(&mm[c0])) * rsqrtf(__ldg(&vv[c0]) + 1e-5f) *
                   __ldg(&gg[c0]) + __ldg(&bb[c0]);
    float y1 = (r1 + __ldg(&b[c1]) - __ldg(&mm[c1])) * rsqrtf(__ldg(&vv[c1]) + 1e-5f) *
                   __ldg(&gg[c1]) + __ldg(&bb[c1]);
    float2 o = make_float2(fmaxf(y0, 0.f), fmaxf(y1, 0.f));
    *(float2*)&xnext[n * 64 + c0] = o;
}

// ============ fused gather-aggregation, 16-wide (layer 3) ============
// warp per dst node; 4 groups of 8 lanes, each group handles one edge per step;
// each lane owns cols (2*c2, 2*c2+1) via half2. shfl_xor(8,16) combines groups.
__global__ void __launch_bounds__(256)
agg16() {
    __shared__ float sh_ex[8][32];
    __shared__ int sh_s[8][32];
    int w = threadIdx.x >> 5;
    int lane = threadIdx.x & 31;
    int n = (blockIdx.x * blockDim.x + threadIdx.x) >> 5;
    if (n >= NN) return;
    int q = lane >> 3;        // edge-group 0..3
    int c2 = lane & 7;        // half2 column index
    float ad = g_ald[n];
    float accx = 0.f, accy = 0.f, den = 0.f;
    const __half2* ph2 = (const __half2*)g_h16;
    int beg = g_off[n], end = g_off[n + 1];
    for (int base = beg; base < end; base += 32) {
        int idx = base + lane;
        bool valid = idx < end;
        int s = valid ? g_csr[idx] : 0;
        float ex = valid ? lrelu_exp(__ldg(&g_als[s]) + ad) : 0.f;
        __syncwarp();
        sh_s[w][lane] = s;
        sh_ex[w][lane] = ex;
        __syncwarp();
        int nk4 = (min(32, end - base) + 3) & ~3;
        for (int j0 = 0; j0 < nk4; j0 += 4) {
            int j = j0 + q;
            int sj = sh_s[w][j];
            float exj = sh_ex[w][j];
            float2 f = __half22float2(__ldg(&ph2[sj * 8 + c2]));
            accx += exj * f.x;
            accy += exj * f.y;
            den += exj;
        }
    }
    accx += __shfl_xor_sync(0xffffffffu, accx, 8);
    accx += __shfl_xor_sync(0xffffffffu, accx, 16);
    accy += __shfl_xor_sync(0xffffffffu, accy, 8);
    accy += __shfl_xor_sync(0xffffffffu, accy, 16);
    den += __shfl_xor_sync(0xffffffffu, den, 8);
    den += __shfl_xor_sync(0xffffffffu, den, 16);
    if (lane < 8) {
        float inv = 1.f / (den + 1e-16f);
        float2 o = make_float2(accx * inv, accy * inv);
        *(float2*)&g_acc[n * 16 + 2 * c2] = o;
    }
}

// ---------------- epilogue layer 3 ----------------
__global__ void ep3(const float* __restrict__ b3, const float* __restrict__ gg,
                    const float* __restrict__ bb, const float* __restrict__ mm,
                    const float* __restrict__ vv, const float* __restrict__ fw1,
                    const float* __restrict__ fb1, const float* __restrict__ fw2,
                    const float* __restrict__ fb2, float* __restrict__ out) {
    int n = blockIdx.x * blockDim.x + threadIdx.x;
    if (n >= NN) return;
    float t[16];
#pragma unroll
    for (int c = 0; c < 16; c++) {
        float y = (g_acc[n * 16 + c] + __ldg(&b3[c]) - __ldg(&mm[c])) *
                      rsqrtf(__ldg(&vv[c]) + 1e-5f) * __ldg(&gg[c]) +
                  __ldg(&bb[c]);
        t[c] = fmaxf(y, 0.f);
    }
    float o = __ldg(&fb2[0]);
#pragma unroll
    for (int oo = 0; oo < 8; oo++) {
        float z = __ldg(&fb1[oo]);
#pragma unroll
        for (int c = 0; c < 16; c++) z += t[c] * __ldg(&fw1[c * 8 + oo]);
        z = fmaxf(z, 0.f);
        o += z * __ldg(&fw2[oo]);
    }
    out[n] = o;
}

// ---------------- launch ----------------
extern "C" void kernel_launch(void* const* d_in, const int* in_sizes, int n_in,
                              void* d_out, int out_size) {
    const float* x = (const float*)d_in[0];
    const int* ei = (const int*)d_in[1];
    const float* W1 = (const float*)d_in[2];
    const float* as1 = (const float*)d_in[3];
    const float* ad1 = (const float*)d_in[4];
    const float* b1 = (const float*)d_in[5];
    const float* g1 = (const float*)d_in[6];
    const float* bb1 = (const float*)d_in[7];
    const float* m1 = (const float*)d_in[8];
    const float* v1 = (const float*)d_in[9];
    const float* W2 = (const float*)d_in[10];
    const float* as2 = (const float*)d_in[11];
    const float* ad2 = (const float*)d_in[12];
    const float* b2 = (const float*)d_in[13];
    const float* g2 = (const float*)d_in[14];
    const float* bb2 = (const float*)d_in[15];
    const float* m2 = (const float*)d_in[16];
    const float* v2 = (const float*)d_in[17];
    const float* W3 = (const float*)d_in[18];
    const float* as3 = (const float*)d_in[19];
    const float* ad3 = (const float*)d_in[20];
    const float* b3 = (const float*)d_in[21];
    const float* g3 = (const float*)d_in[22];
    const float* bb3 = (const float*)d_in[23];
    const float* m3 = (const float*)d_in[24];
    const float* v3 = (const float*)d_in[25];
    const float* fw1 = (const float*)d_in[26];
    const float* fb1 = (const float*)d_in[27];
    const float* fw2 = (const float*)d_in[28];
    const float* fb2 = (const float*)d_in[29];
    float* out = (float*)d_out;

    float* ph = nullptr;
    float* px2 = nullptr;
    int* pdeg = nullptr;
    cudaGetSymbolAddress((void**)&ph, g_h);
    cudaGetSymbolAddress((void**)&px2, g_x2);
    cudaGetSymbolAddress((void**)&pdeg, g_deg);

    const int TB = 256;
    int nblk = (NN + TB - 1) / TB;
    int eblk = (ETOT + TB - 1) / TB;
    int aggblk = (NN * 32 + TB - 1) / TB;
    int g64blk = (NN + 127) / 128;

    // ---- CSR build ----
    cudaMemsetAsync(pdeg, 0, NN * sizeof(int));
    hist_kernel<<<eblk, TB>>>(ei);
    scan_kernel<<<1, 1024>>>();
    scatter_kernel<<<eblk, TB>>>(ei);

    // ---- Layer 1 ----
    gemm64<128><<<g64blk, TB>>>(x, W1, as1, ad1);
    agg64<<<aggblk, TB>>>(b1, g1, bb1, m1, v1, px2);

    // ---- Layer 2 ----
    gemm64<64><<<g64blk, TB>>>(px2, W2, as2, ad2);
    agg64<<<aggblk, TB>>>(b2, g2, bb2, m2, v2, px2);

    // ---- Layer 3 ----
    gemm16<<<(NN + 63) / 64, TB>>>(px2, W3, ph);
    al1<<<nblk, TB>>>(ph, as3, ad3);
    agg16<<<aggblk, TB>>>();
    ep3<<<nblk, TB>>>(b3, g3, bb3, m3, v3, fw1, fb1, fw2, fb2, out);
}

// round 8
// speedup vs baseline: 1.8536x; 1.1466x over previous
#include <cuda_runtime.h>
#include <cuda_fp16.h>
#include <math.h>

#define NN 50000
#define EE 1600000
#define ETOT (EE + NN)
#define G64BLK ((NN + 127) / 128)
#define EBLK ((ETOT + 255) / 256)

// ---------------- scratch ----------------
__device__ __half g_h16[NN * 64];    // fp16 h for gather (all layers)
__device__ float  g_x2[NN * 64];
__device__ float  g_als[NN * 4];
__device__ float  g_ald[NN * 4];
__device__ float  g_acc[NN * 16];
__device__ int    g_deg[NN];
__device__ int    g_off[NN + 1];
__device__ int    g_cur[NN];
__device__ int    g_csr[ETOT];

// ================= CSR build =================
__global__ void hist_kernel(const int* __restrict__ ei) {
    int e = blockIdx.x * blockDim.x + threadIdx.x;
    if (e >= ETOT) return;
    int d = (e < EE) ? ei[EE + e] : (e - EE);
    atomicAdd(&g_deg[d], 1);
}

__global__ void scan_kernel() {
    __shared__ int partial[1024];
    int t = threadIdx.x;
    const int C = (NN + 1023) / 1024;
    int b0 = t * C;
    int b1 = min(b0 + C, NN);
    int sum = 0;
    for (int i = b0; i < b1; i++) sum += g_deg[i];
    partial[t] = sum;
    __syncthreads();
    for (int off = 1; off < 1024; off <<= 1) {
        int v = (t >= off) ? partial[t - off] : 0;
        __syncthreads();
        partial[t] += v;
        __syncthreads();
    }
    int run = (t == 0) ? 0 : partial[t - 1];
    for (int i = b0; i < b1; i++) {
        g_off[i] = run;
        g_cur[i] = run;
        run += g_deg[i];
    }
    if (t == 1023) g_off[NN] = run;
}

// ===== fused: layer-1 GEMM (blocks [0, G64BLK)) || CSR scatter (rest) =====
__global__ void __launch_bounds__(256)
fused_gemm1_scatter(const float* __restrict__ X, const float* __restrict__ W,
                    const float* __restrict__ a_s, const float* __restrict__ a_d,
                    const int* __restrict__ ei) {
    constexpr int IN = 128;
    constexpr int KT = 32;
    constexpr int SXS = 132;
    __shared__ float sW[KT][64];
    __shared__ float sX2[KT][SXS];
    int t = threadIdx.x;

    if (blockIdx.x >= G64BLK) {
        // ---- scatter part ----
        int e = (blockIdx.x - G64BLK) * 256 + t;
        if (e < ETOT) {
            int s, d;
            if (e < EE) { s = ei[e]; d = ei[EE + e]; } else { s = e - EE; d = s; }
            int pos = atomicAdd(&g_cur[d], 1);
            g_csr[pos] = s;
        }
        return;
    }

    // ---- GEMM part ----
    int tx = t & 15, ty = t >> 4;
    int row0 = blockIdx.x * 128;
    float acc[8][4];
#pragma unroll
    for (int r = 0; r < 8; r++)
#pragma unroll
        for (int c = 0; c < 4; c++) acc[r][c] = 0.f;

    for (int kt = 0; kt < IN; kt += KT) {
#pragma unroll
        for (int i = t; i < KT * 16; i += 256) {
            int kk = i >> 4;
            int c4 = (i & 15) << 2;
            *(float4*)&sW[kk][c4] = *(const float4*)&W[(kt + kk) * 64 + c4];
        }
#pragma unroll
        for (int i = t; i < 128 * (KT / 4); i += 256) {
            int r = i >> 3;
            int k4 = (i & 7) << 2;
            int gr = row0 + r;
            float4 v = (gr < NN) ? *(const float4*)&X[gr * IN + kt + k4]
                                 : make_float4(0.f, 0.f, 0.f, 0.f);
            sX2[k4 + 0][r] = v.x;
            sX2[k4 + 1][r] = v.y;
            sX2[k4 + 2][r] = v.z;
            sX2[k4 + 3][r] = v.w;
        }
        __syncthreads();
#pragma unroll
        for (int k = 0; k < KT; k++) {
            float4 w4 = *(float4*)&sW[k][tx * 4];
            float4 xa = *(float4*)&sX2[k][ty * 8];
            float4 xb = *(float4*)&sX2[k][ty * 8 + 4];
            float xr[8] = {xa.x, xa.y, xa.z, xa.w, xb.x, xb.y, xb.z, xb.w};
#pragma unroll
            for (int r = 0; r < 8; r++) {
                acc[r][0] += xr[r] * w4.x;
                acc[r][1] += xr[r] * w4.y;
                acc[r][2] += xr[r] * w4.z;
                acc[r][3] += xr[r] * w4.w;
            }
        }
        __syncthreads();
    }

    int h = tx >> 2;
    float4 asv = *(const float4*)&a_s[h * 16 + (tx & 3) * 4];
    float4 adv = *(const float4*)&a_d[h * 16 + (tx & 3) * 4];
    __half2* h2out = (__half2*)g_h16;
#pragma unroll
    for (int r = 0; r < 8; r++) {
        int gr = row0 + ty * 8 + r;
        float ps = acc[r][0] * asv.x + acc[r][1] * asv.y + acc[r][2] * asv.z + acc[r][3] * asv.w;
        float pd = acc[r][0] * adv.x + acc[r][1] * adv.y + acc[r][2] * adv.z + acc[r][3] * adv.w;
        ps += __shfl_xor_sync(0xffffffffu, ps, 1);
        ps += __shfl_xor_sync(0xffffffffu, ps, 2);
        pd += __shfl_xor_sync(0xffffffffu, pd, 1);
        pd += __shfl_xor_sync(0xffffffffu, pd, 2);
        if (gr < NN) {
            h2out[(gr * 64 + tx * 4) >> 1] = __floats2half2_rn(acc[r][0], acc[r][1]);
            h2out[((gr * 64 + tx * 4) >> 1) + 1] = __floats2half2_rn(acc[r][2], acc[r][3]);
            if ((tx & 3) == 0) {
                g_als[gr * 4 + h] = ps;
                g_ald[gr * 4 + h] = pd;
            }
        }
    }
}

// ------- GEMM 64-wide (layer 2), 128-row tile, fused al + fp16 out ----
template <int IN>
__global__ void __launch_bounds__(256)
gemm64(const float* __restrict__ X, const float* __restrict__ W,
       const float* __restrict__ a_s, const float* __restrict__ a_d) {
    constexpr int KT = 32;
    constexpr int SXS = 132;
    __shared__ float sW[KT][64];
    __shared__ float sX2[KT][SXS];
    int t = threadIdx.x;
    int tx = t & 15, ty = t >> 4;
    int row0 = blockIdx.x * 128;
    float acc[8][4];
#pragma unroll
    for (int r = 0; r < 8; r++)
#pragma unroll
        for (int c = 0; c < 4; c++) acc[r][c] = 0.f;

    for (int kt = 0; kt < IN; kt += KT) {
#pragma unroll
        for (int i = t; i < KT * 16; i += 256) {
            int kk = i >> 4;
            int c4 = (i & 15) << 2;
            *(float4*)&sW[kk][c4] = *(const float4*)&W[(kt + kk) * 64 + c4];
        }
#pragma unroll
        for (int i = t; i < 128 * (KT / 4); i += 256) {
            int r = i >> 3;
            int k4 = (i & 7) << 2;
            int gr = row0 + r;
            float4 v = (gr < NN) ? *(const float4*)&X[gr * IN + kt + k4]
                                 : make_float4(0.f, 0.f, 0.f, 0.f);
            sX2[k4 + 0][r] = v.x;
            sX2[k4 + 1][r] = v.y;
            sX2[k4 + 2][r] = v.z;
            sX2[k4 + 3][r] = v.w;
        }
        __syncthreads();
#pragma unroll
        for (int k = 0; k < KT; k++) {
            float4 w4 = *(float4*)&sW[k][tx * 4];
            float4 xa = *(float4*)&sX2[k][ty * 8];
            float4 xb = *(float4*)&sX2[k][ty * 8 + 4];
            float xr[8] = {xa.x, xa.y, xa.z, xa.w, xb.x, xb.y, xb.z, xb.w};
#pragma unroll
            for (int r = 0; r < 8; r++) {
                acc[r][0] += xr[r] * w4.x;
                acc[r][1] += xr[r] * w4.y;
                acc[r][2] += xr[r] * w4.z;
                acc[r][3] += xr[r] * w4.w;
            }
        }
        __syncthreads();
    }

    int h = tx >> 2;
    float4 asv = *(const float4*)&a_s[h * 16 + (tx & 3) * 4];
    float4 adv = *(const float4*)&a_d[h * 16 + (tx & 3) * 4];
    __half2* h2out = (__half2*)g_h16;
#pragma unroll
    for (int r = 0; r < 8; r++) {
        int gr = row0 + ty * 8 + r;
        float ps = acc[r][0] * asv.x + acc[r][1] * asv.y + acc[r][2] * asv.z + acc[r][3] * asv.w;
        float pd = acc[r][0] * adv.x + acc[r][1] * adv.y + acc[r][2] * adv.z + acc[r][3] * adv.w;
        ps += __shfl_xor_sync(0xffffffffu, ps, 1);
        ps += __shfl_xor_sync(0xffffffffu, ps, 2);
        pd += __shfl_xor_sync(0xffffffffu, pd, 1);
        pd += __shfl_xor_sync(0xffffffffu, pd, 2);
        if (gr < NN) {
            h2out[(gr * 64 + tx * 4) >> 1] = __floats2half2_rn(acc[r][0], acc[r][1]);
            h2out[((gr * 64 + tx * 4) >> 1) + 1] = __floats2half2_rn(acc[r][2], acc[r][3]);
            if ((tx & 3) == 0) {
                g_als[gr * 4 + h] = ps;
                g_ald[gr * 4 + h] = pd;
            }
        }
    }
}

// ------- GEMM layer 3 (64->16): fused al epilogue, fp16-only output -------
__global__ void gemm16(const float* __restrict__ X, const float* __restrict__ W,
                       const float* __restrict__ a_s, const float* __restrict__ a_d) {
    constexpr int IN = 64, OUT = 16;
    constexpr int RB = 64;
    __shared__ float sW[IN * OUT];
    __shared__ float sX[RB * IN];
    int t = threadIdx.x;
    int tx = t & 15, ty = t >> 4;
    int row0 = blockIdx.x * RB;

    for (int i = t; i < IN * OUT; i += 256) sW[i] = W[i];
    for (int i = t; i < RB * IN; i += 256) {
        int r = row0 + i / IN;
        sX[i] = (r < NN) ? X[r * IN + (i % IN)] : 0.f;
    }
    __syncthreads();

    float acc[4];
#pragma unroll
    for (int rr = 0; rr < 4; rr++) acc[rr] = 0.f;
    const float* xs = &sX[ty * 4 * IN];
    for (int k = 0; k < IN; k++) {
        float wv = sW[k * OUT + tx];
#pragma unroll
        for (int rr = 0; rr < 4; rr++) acc[rr] += xs[rr * IN + k] * wv;
    }
    float asx = __ldg(&a_s[tx]), adx = __ldg(&a_d[tx]);
#pragma unroll
    for (int rr = 0; rr < 4; rr++) {
        int r = row0 + ty * 4 + rr;
        float ps = acc[rr] * asx;
        float pd = acc[rr] * adx;
#pragma unroll
        for (int off = 1; off < 16; off <<= 1) {
            ps += __shfl_xor_sync(0xffffffffu, ps, off);
            pd += __shfl_xor_sync(0xffffffffu, pd, off);
        }
        if (r < NN) {
            g_h16[r * OUT + tx] = __float2half_rn(acc[rr]);
            if (tx == 0) {
                g_als[r] = ps;
                g_ald[r] = pd;
            }
        }
    }
}

__device__ __forceinline__ float lrelu_exp(float v) {
    v = (v > 0.f) ? v : 0.2f * v;
    return __expf(v);
}

// ============ fused gather-aggregation, 64-wide (layers 1 & 2) ============
// warp per dst node; lane owns half2 cols (2*lane, 2*lane+1), head = lane>>3.
// (src, ex) packed as float2 in smem -> 1 LDS.64 per edge in hot loop.
__global__ void __launch_bounds__(256)
agg64(const float* __restrict__ b,
      const float* __restrict__ gg, const float* __restrict__ bb,
      const float* __restrict__ mm, const float* __restrict__ vv,
      float* __restrict__ xnext) {
    __shared__ float2 sh_sex[8][4][33];
    int w = threadIdx.x >> 5;
    int lane = threadIdx.x & 31;
    int n = (blockIdx.x * blockDim.x + threadIdx.x) >> 5;
    if (n >= NN) return;
    int c0 = 2 * lane;
    int h = lane >> 3;
    float4 ad4 = *(const float4*)&g_ald[n * 4];
    float accx = 0.f, accy = 0.f, den = 0.f;
    const __half2* ph2 = (const __half2*)g_h16;
    int beg = g_off[n], end = g_off[n + 1];
    for (int base = beg; base < end; base += 32) {
        int idx = base + lane;
        bool valid = idx < end;
        int s = valid ? g_csr[idx] : 0;
        float4 as4 = *(const float4*)&g_als[s * 4];
        float sf = __int_as_float(s);
        float e0 = valid ? lrelu_exp(as4.x + ad4.x) : 0.f;
        float e1 = valid ? lrelu_exp(as4.y + ad4.y) : 0.f;
        float e2 = valid ? lrelu_exp(as4.z + ad4.z) : 0.f;
        float e3 = valid ? lrelu_exp(as4.w + ad4.w) : 0.f;
        __syncwarp();
        sh_sex[w][0][lane] = make_float2(sf, e0);
        sh_sex[w][1][lane] = make_float2(sf, e1);
        sh_sex[w][2][lane] = make_float2(sf, e2);
        sh_sex[w][3][lane] = make_float2(sf, e3);
        __syncwarp();
        int nk8 = (min(32, end - base) + 7) & ~7;
        for (int j0 = 0; j0 < nk8; j0 += 8) {
#pragma unroll
            for (int jj = 0; jj < 8; jj++) {
                int j = j0 + jj;
                float2 p = sh_sex[w][h][j];
                int sj = __float_as_int(p.x);
                float ex = p.y;
                float2 f = __half22float2(__ldg(&ph2[sj * 32 + lane]));
                accx += ex * f.x;
                accy += ex * f.y;
                den += ex;
            }
        }
    }
    float inv = 1.f / (den + 1e-16f);
    float r0 = accx * inv;
    float r1 = accy * inv;
    int c1 = c0 + 1;
    float y0 = (r0 + __ldg(&b[c0]) - __ldg(&mm[c0])) * rsqrtf(__ldg(&vv[c0]) + 1e-5f) *
                   __ldg(&gg[c0]) + __ldg(&bb[c0]);
    float y1 = (r1 + __ldg(&b[c1]) - __ldg(&mm[c1])) * rsqrtf(__ldg(&vv[c1]) + 1e-5f) *
                   __ldg(&gg[c1]) + __ldg(&bb[c1]);
    float2 o = make_float2(fmaxf(y0, 0.f), fmaxf(y1, 0.f));
    *(float2*)&xnext[n * 64 + c0] = o;
}

// ============ fused gather-aggregation, 16-wide (layer 3) ============
__global__ void __launch_bounds__(256)
agg16() {
    __shared__ float2 sh_sex[8][33];
    int w = threadIdx.x >> 5;
    int lane = threadIdx.x & 31;
    int n = (blockIdx.x * blockDim.x + threadIdx.x) >> 5;
    if (n >= NN) return;
    int q = lane >> 3;        // edge-group 0..3
    int c2 = lane & 7;        // half2 column index
    float ad = g_ald[n];
    float accx = 0.f, accy = 0.f, den = 0.f;
    const __half2* ph2 = (const __half2*)g_h16;
    int beg = g_off[n], end = g_off[n + 1];
    for (int base = beg; base < end; base += 32) {
        int idx = base + lane;
        bool valid = idx < end;
        int s = valid ? g_csr[idx] : 0;
        float ex = valid ? lrelu_exp(__ldg(&g_als[s]) + ad) : 0.f;
        __syncwarp();
        sh_sex[w][lane] = make_float2(__int_as_float(s), ex);
        __syncwarp();
        int nk4 = (min(32, end - base) + 3) & ~3;
        for (int j0 = 0; j0 < nk4; j0 += 4) {
            int j = j0 + q;
            float2 p = sh_sex[w][j];
            int sj = __float_as_int(p.x);
            float exj = p.y;
            float2 f = __half22float2(__ldg(&ph2[sj * 8 + c2]));
            accx += exj * f.x;
            accy += exj * f.y;
            den += exj;
        }
    }
    accx += __shfl_xor_sync(0xffffffffu, accx, 8);
    accx += __shfl_xor_sync(0xffffffffu, accx, 16);
    accy += __shfl_xor_sync(0xffffffffu, accy, 8);
    accy += __shfl_xor_sync(0xffffffffu, accy, 16);
    den += __shfl_xor_sync(0xffffffffu, den, 8);
    den += __shfl_xor_sync(0xffffffffu, den, 16);
    if (lane < 8) {
        float inv = 1.f / (den + 1e-16f);
        float2 o = make_float2(accx * inv, accy * inv);
        *(float2*)&g_acc[n * 16 + 2 * c2] = o;
    }
}

// ---------------- epilogue layer 3 ----------------
__global__ void ep3(const float* __restrict__ b3, const float* __restrict__ gg,
                    const float* __restrict__ bb, const float* __restrict__ mm,
                    const float* __restrict__ vv, const float* __restrict__ fw1,
                    const float* __restrict__ fb1, const float* __restrict__ fw2,
                    const float* __restrict__ fb2, float* __restrict__ out) {
    int n = blockIdx.x * blockDim.x + threadIdx.x;
    if (n >= NN) return;
    float t[16];
#pragma unroll
    for (int c = 0; c < 16; c++) {
        float y = (g_acc[n * 16 + c] + __ldg(&b3[c]) - __ldg(&mm[c])) *
                      rsqrtf(__ldg(&vv[c]) + 1e-5f) * __ldg(&gg[c]) +
                  __ldg(&bb[c]);
        t[c] = fmaxf(y, 0.f);
    }
    float o = __ldg(&fb2[0]);
#pragma unroll
    for (int oo = 0; oo < 8; oo++) {
        float z = __ldg(&fb1[oo]);
#pragma unroll
        for (int c = 0; c < 16; c++) z += t[c] * __ldg(&fw1[c * 8 + oo]);
        z = fmaxf(z, 0.f);
        o += z * __ldg(&fw2[oo]);
    }
    out[n] = o;
}

// ---------------- launch ----------------
extern "C" void kernel_launch(void* const* d_in, const int* in_sizes, int n_in,
                              void* d_out, int out_size) {
    const float* x = (const float*)d_in[0];
    const int* ei = (const int*)d_in[1];
    const float* W1 = (const float*)d_in[2];
    const float* as1 = (const float*)d_in[3];
    const float* ad1 = (const float*)d_in[4];
    const float* b1 = (const float*)d_in[5];
    const float* g1 = (const float*)d_in[6];
    const float* bb1 = (const float*)d_in[7];
    const float* m1 = (const float*)d_in[8];
    const float* v1 = (const float*)d_in[9];
    const float* W2 = (const float*)d_in[10];
    const float* as2 = (const float*)d_in[11];
    const float* ad2 = (const float*)d_in[12];
    const float* b2 = (const float*)d_in[13];
    const float* g2 = (const float*)d_in[14];
    const float* bb2 = (const float*)d_in[15];
    const float* m2 = (const float*)d_in[16];
    const float* v2 = (const float*)d_in[17];
    const float* W3 = (const float*)d_in[18];
    const float* as3 = (const float*)d_in[19];
    const float* ad3 = (const float*)d_in[20];
    const float* b3 = (const float*)d_in[21];
    const float* g3 = (const float*)d_in[22];
    const float* bb3 = (const float*)d_in[23];
    const float* m3 = (const float*)d_in[24];
    const float* v3 = (const float*)d_in[25];
    const float* fw1 = (const float*)d_in[26];
    const float* fb1 = (const float*)d_in[27];
    const float* fw2 = (const float*)d_in[28];
    const float* fb2 = (const float*)d_in[29];
    float* out = (float*)d_out;

    float* px2 = nullptr;
    int* pdeg = nullptr;
    cudaGetSymbolAddress((void**)&px2, g_x2);
    cudaGetSymbolAddress((void**)&pdeg, g_deg);

    const int TB = 256;
    int nblk = (NN + TB - 1) / TB;
    int aggblk = (NN * 32 + TB - 1) / TB;

    // ---- CSR: hist + scan, then scatter fused with layer-1 GEMM ----
    cudaMemsetAsync(pdeg, 0, NN * sizeof(int));
    hist_kernel<<<EBLK, TB>>>(ei);
    scan_kernel<<<1, 1024>>>();

    // ---- Layer 1 GEMM || CSR scatter ----
    fused_gemm1_scatter<<<G64BLK + EBLK, TB>>>(x, W1, as1, ad1, ei);
    agg64<<<aggblk, TB>>>(b1, g1, bb1, m1, v1, px2);

    // ---- Layer 2 ----
    gemm64<64><<<G64BLK, TB>>>(px2, W2, as2, ad2);
    agg64<<<aggblk, TB>>>(b2, g2, bb2, m2, v2, px2);

    // ---- Layer 3 ----
    gemm16<<<(NN + 63) / 64, TB>>>(px2, W3, as3, ad3);
    agg16<<<aggblk, TB>>>();
    ep3<<<nblk, TB>>>(b3, g3, bb3, m3, v3, fw1, fb1, fw2, fb2, out);
}